// round 10
// baseline (speedup 1.0000x reference)
#include <cuda_runtime.h>
#include <cuda_fp16.h>
#include <math.h>
#include <stdint.h>

#define BATCH   64
#define HIMG    28
#define WIMG    28
#define DIM     384
#define HEADS   12
#define HD      32
#define WIN     7
#define SHIFT   3
#define NTOK    49
#define NWIN    16
#define ROWS    (BATCH*NWIN*NTOK)   // 50176
#define MLPH    1536

// ---------------- scratch ----------------------------------------------------
__device__ __half g_xw [ROWS*DIM];
__device__ __half g_qkv[ROWS*3*DIM];
__device__ __half g_att[ROWS*DIM];
__device__ float  g_x1 [ROWS*DIM];
__device__ __half g_z  [ROWS*DIM];
__device__ __half g_hid[(size_t)ROWS*MLPH];
// fp16 weights
__device__ __half g_wq[3*DIM*DIM];
__device__ __half g_wp[DIM*DIM];
__device__ __half g_w1[MLPH*DIM];
__device__ __half g_w2[DIM*MLPH];
// combined bias+mask table: [4 window types][12 heads][49][49]
__device__ float g_tbl[48*NTOK*NTOK];

// ---------------- helpers ------------------------------------------------------
__device__ __forceinline__ uint32_t smem_u32(const void* p) {
    uint32_t a;
    asm("{ .reg .u64 t; cvta.to.shared.u64 t, %1; cvt.u32.u64 %0, t; }" : "=r"(a) : "l"(p));
    return a;
}
__device__ __forceinline__ void cp16(uint32_t s, const void* g) {
    asm volatile("cp.async.cg.shared.global [%0], [%1], 16;" :: "r"(s), "l"(g));
}
#define CP_COMMIT() asm volatile("cp.async.commit_group;" ::: "memory")
#define CP_WAIT1()  asm volatile("cp.async.wait_group 1;" ::: "memory")

__device__ __forceinline__ void mma_f16(float* d, const uint32_t* a, const uint32_t* b) {
    asm volatile(
        "mma.sync.aligned.m16n8k16.row.col.f32.f16.f16.f32 "
        "{%0,%1,%2,%3}, {%4,%5,%6,%7}, {%8,%9}, {%0,%1,%2,%3};"
        : "+f"(d[0]), "+f"(d[1]), "+f"(d[2]), "+f"(d[3])
        : "r"(a[0]), "r"(a[1]), "r"(a[2]), "r"(a[3]), "r"(b[0]), "r"(b[1]));
}
__device__ __forceinline__ void ldsm4(uint32_t& r0, uint32_t& r1, uint32_t& r2,
                                      uint32_t& r3, uint32_t addr) {
    asm volatile("ldmatrix.sync.aligned.m8n8.x4.shared.b16 {%0,%1,%2,%3}, [%4];"
        : "=r"(r0), "=r"(r1), "=r"(r2), "=r"(r3) : "r"(addr));
}

// ---------------- weight prep: fp32 -> fp16 (all 4 matrices, 1 launch) ---------
__global__ void wprep_all(const float* s0, __half* d0, int n0,
                          const float* s1, __half* d1, int n1,
                          const float* s2, __half* d2, int n2,
                          const float* s3, __half* d3, int n3) {
    int i = blockIdx.x * blockDim.x + threadIdx.x;
    const float* s; __half* d; int j = i;
    if (j < n0) { s = s0; d = d0; }
    else { j -= n0; if (j < n1) { s = s1; d = d1; }
    else { j -= n1; if (j < n2) { s = s2; d = d2; }
    else { j -= n2; if (j >= n3) return; s = s3; d = d3; } } }
    float4 v = ((const float4*)s)[j];
    __half2* dp = (__half2*)(d + j*4);
    dp[0] = __floats2half2_rn(v.x, v.y);
    dp[1] = __floats2half2_rn(v.z, v.w);
}

// ---------------- bias+mask table build ----------------------------------------
__global__ void tbuild_kernel(const float* __restrict__ btab, float* __restrict__ tbl) {
    int th = blockIdx.x;
    int type = th / HEADS, h = th % HEADS;
    int eh = (type >> 1) & 1, ew = type & 1;
    for (int e = threadIdx.x; e < NTOK*NTOK; e += blockDim.x) {
        int n = e / NTOK, m = e % NTOK;
        int i1 = n/7, j1 = n%7, i2 = m/7, j2 = m%7;
        float v = btab[((i1 - i2 + 6)*13 + (j1 - j2 + 6))*HEADS + h];
        int r1 = (eh ? (i1 < 4 ? 1 : 2) : 0) * 3 + (ew ? (j1 < 4 ? 1 : 2) : 0);
        int r2 = (eh ? (i2 < 4 ? 1 : 2) : 0) * 3 + (ew ? (j2 < 4 ? 1 : 2) : 0);
        if (r1 != r2) v -= 100.f;
        tbl[th*NTOK*NTOK + e] = v;
    }
}

// ---------------- LayerNorm (optionally fused shift+window gather), half out ---
template<int GATHER>
__global__ void ln_kernel(const float* __restrict__ x, const float* __restrict__ w,
                          const float* __restrict__ b, __half* __restrict__ out) {
    int r = blockIdx.x;
    int src = r;
    if (GATHER) {
        int bb  = r / (NWIN*NTOK);
        int rem = r % (NWIN*NTOK);
        int win = rem / NTOK, n = rem % NTOK;
        int wh = win / 4, ww = win % 4;
        int i = n / 7, j = n % 7;
        int sh = (wh*7 + i + SHIFT) % HIMG;
        int sw = (ww*7 + j + SHIFT) % WIMG;
        src = bb*(HIMG*WIMG) + sh*WIMG + sw;
    }
    const float* xp = x + (size_t)src * DIM;
    int tid = threadIdx.x;
    float v0 = xp[tid], v1 = xp[tid+128], v2 = xp[tid+256];
    float s = v0 + v1 + v2;
    __shared__ float red[4];
    #pragma unroll
    for (int o = 16; o; o >>= 1) s += __shfl_xor_sync(~0u, s, o);
    if ((tid & 31) == 0) red[tid >> 5] = s;
    __syncthreads();
    float mean = (red[0]+red[1]+red[2]+red[3]) * (1.0f/DIM);
    float d0 = v0-mean, d1 = v1-mean, d2 = v2-mean;
    float q = d0*d0 + d1*d1 + d2*d2;
    #pragma unroll
    for (int o = 16; o; o >>= 1) q += __shfl_xor_sync(~0u, q, o);
    __syncthreads();
    if ((tid & 31) == 0) red[tid >> 5] = q;
    __syncthreads();
    float var = (red[0]+red[1]+red[2]+red[3]) * (1.0f/DIM);
    float inv = rsqrtf(var + 1e-5f);
    __half* op = out + (size_t)r * DIM;
    op[tid]     = __float2half_rn(d0*inv*w[tid]     + b[tid]);
    op[tid+128] = __float2half_rn(d1*inv*w[tid+128] + b[tid+128]);
    op[tid+256] = __float2half_rn(d2*inv*w[tid+256] + b[tid+256]);
}

// ---------------- pipelined fp16 GEMM, CTA tile 256x128, 8 warps (4x2) ---------
// warp tile 64x64, BK=64 halves, 3-stage cp.async (48KB/stage), 1 sync/k-tile.
#define STB 49152          // bytes per stage: A 32768 + B 16384
#define SMEM_T (3*STB)     // 147456 bytes
template<int MODE>
__global__ void __launch_bounds__(256, 1)
mma_gemm(const __half* __restrict__ A, const __half* __restrict__ W,
         const float* __restrict__ bias, const float* __restrict__ res,
         void* __restrict__ outv, int M, int N, int K) {
    extern __shared__ __align__(16) uint32_t smem[];
    uint32_t sbase = smem_u32(smem);
    int tid  = threadIdx.x;
    int wid  = tid >> 5, lane = tid & 31;
    int wm   = wid >> 1, wn = wid & 1;           // warp grid 4x2
    int q    = lane >> 2, c = lane & 3;
    int m0   = blockIdx.y * 256, n0 = blockIdx.x * 128;

    int sr = tid >> 3;          // 0..31 staging row base
    int sc = tid & 7;           // 16B chunk along k

    // ldmatrix per-lane geometry
    int lrow = (lane & 7) + ((lane >> 3) & 1) * 8;   // 0..15
    int lch  = lane >> 4;                            // 0 or 1
    int lb7  = lane & 7;

    const __half* Ag0 = A + (size_t)(m0 + sr) * K + sc*8;
    const __half* Wg0 = W + (size_t)(n0 + sr) * K + sc*8;

    float acc[4][8][4];
    #pragma unroll
    for (int i = 0; i < 4; i++)
        #pragma unroll
        for (int j = 0; j < 8; j++)
            #pragma unroll
            for (int e = 0; e < 4; e++) acc[i][j][e] = 0.f;

    const int T = K >> 6;       // BK = 64 halves

    auto load_tile = [&](int t) {
        uint32_t sb = sbase + (uint32_t)(t % 3) * STB;
        const __half* Ag = Ag0 + t*64;
        const __half* Wg = Wg0 + t*64;
        #pragma unroll
        for (int i = 0; i < 8; i++) {           // A: 256 rows
            int m = sr + i*32;
            uint32_t off = (uint32_t)(m*128 + ((sc*16) ^ ((m & 7) * 16)));
            cp16(sb + off, Ag + (size_t)i*32*K);
        }
        #pragma unroll
        for (int i = 0; i < 4; i++) {           // B: 128 rows
            int m = sr + i*32;
            uint32_t off = (uint32_t)(m*128 + ((sc*16) ^ ((m & 7) * 16)));
            cp16(sb + 32768 + off, Wg + (size_t)i*32*K);
        }
    };

    load_tile(0); CP_COMMIT();
    load_tile(1); CP_COMMIT();

    for (int t = 0; t < T; t++) {
        CP_WAIT1();
        __syncthreads();
        if (t + 2 < T) load_tile(t + 2);
        CP_COMMIT();

        uint32_t stage = sbase + (uint32_t)(t % 3) * STB;
        uint32_t abase = stage + (uint32_t)((wm*64 + lrow) * 128);
        uint32_t bbase = stage + 32768 + (uint32_t)((wn*64 + lrow) * 128);
        #pragma unroll
        for (int ks = 0; ks < 4; ks++) {       // 4 x k16
            uint32_t sw = (uint32_t)(((ks*2 + lch) ^ lb7) * 16);
            uint32_t af[4][4];
            #pragma unroll
            for (int mi = 0; mi < 4; mi++)
                ldsm4(af[mi][0], af[mi][1], af[mi][2], af[mi][3],
                      abase + mi*2048 + sw);
            uint32_t bf[8][2];
            #pragma unroll
            for (int nb = 0; nb < 4; nb++) {
                uint32_t r0, r1, r2, r3;
                ldsm4(r0, r1, r2, r3, bbase + nb*2048 + sw);
                bf[2*nb][0]   = r0; bf[2*nb+1][0] = r1;
                bf[2*nb][1]   = r2; bf[2*nb+1][1] = r3;
            }
            #pragma unroll
            for (int mi = 0; mi < 4; mi++)
                #pragma unroll
                for (int ni = 0; ni < 8; ni++)
                    mma_f16(acc[mi][ni], af[mi], bf[ni]);
        }
    }

    // ---- epilogue ----
    #pragma unroll
    for (int mi = 0; mi < 4; mi++) {
        int r0 = m0 + wm*64 + mi*16 + q;
        int r1 = r0 + 8;
        size_t or0, or1;
        if (MODE == 3) {
            #pragma unroll
            for (int half_ = 0; half_ < 2; half_++) {
                int m = half_ ? r1 : r0;
                int bbi = m / (NWIN*NTOK);
                int rem = m % (NWIN*NTOK);
                int win = rem / NTOK, n = rem % NTOK;
                int wh = win >> 2, ww = win & 3, ii = n / 7, jj = n % 7;
                int dh = (wh*7 + ii + SHIFT) % HIMG;
                int dw = (ww*7 + jj + SHIFT) % WIMG;
                size_t o = (size_t)bbi*(HIMG*WIMG) + dh*WIMG + dw;
                if (half_) or1 = o; else or0 = o;
            }
        } else {
            or0 = (size_t)r0; or1 = (size_t)r1;
        }
        #pragma unroll
        for (int ni = 0; ni < 8; ni++) {
            int col = n0 + wn*64 + ni*8 + 2*c;
            float2 bv = *(const float2*)&bias[col];
            float v00 = acc[mi][ni][0] + bv.x, v01 = acc[mi][ni][1] + bv.y;
            float v10 = acc[mi][ni][2] + bv.x, v11 = acc[mi][ni][3] + bv.y;
            if (MODE == 1) {
                v00 = 0.5f*v00*(1.0f + erff(v00*0.70710678118654752f));
                v01 = 0.5f*v01*(1.0f + erff(v01*0.70710678118654752f));
                v10 = 0.5f*v10*(1.0f + erff(v10*0.70710678118654752f));
                v11 = 0.5f*v11*(1.0f + erff(v11*0.70710678118654752f));
            }
            if (MODE >= 2) {
                float2 ra = *(const float2*)&res[or0*N + col];
                float2 rb = *(const float2*)&res[or1*N + col];
                v00 += ra.x; v01 += ra.y; v10 += rb.x; v11 += rb.y;
            }
            if (MODE == 0 || MODE == 1) {
                __half* O = (__half*)outv;
                *(__half2*)&O[or0*N + col] = __floats2half2_rn(v00, v01);
                *(__half2*)&O[or1*N + col] = __floats2half2_rn(v10, v11);
            } else {
                float* O = (float*)outv;
                float2 o0; o0.x = v00; o0.y = v01;
                float2 o1; o1.x = v10; o1.y = v11;
                *(float2*)&O[or0*N + col] = o0;
                *(float2*)&O[or1*N + col] = o1;
            }
        }
    }
}

// ---------------- fp16 tensor-core windowed attention --------------------------
#define QS2 20
#define VS2 36
#define PS2 36
__global__ void __launch_bounds__(128)
attn_mma(const __half* __restrict__ qkv, const float* __restrict__ tbl,
         __half* __restrict__ out) {
    int bw = blockIdx.x, h = blockIdx.y;
    __shared__ uint32_t sm[6752];
    uint32_t* qs  = sm;                 // 1280
    uint32_t* kkp = sm + 1280;          // 1120
    uint32_t* vvT = sm + 2400;          // 1152
    float*    tsm = (float*)(sm + 3552);// 3200 floats
    uint32_t* ps  = sm;                 // 2304 (aliases qs+kk)
    __half* qsh = (__half*)qs;
    __half* kkh = (__half*)kkp;
    __half* vvh = (__half*)vvT;
    int tid = threadIdx.x;
    int wid = tid >> 5, lane = tid & 31;
    int q8 = lane >> 2, c4 = lane & 3;
    const float scale = 0.17677669529663689f;

    for (int idx = tid; idx < 64*32; idx += 128) {
        int n = idx >> 5, d = idx & 31;
        float qv = 0.f, kv = 0.f, vv_ = 0.f;
        if (n < NTOK) {
            size_t base = (size_t)(bw*NTOK + n)*(3*DIM) + h*HD + d;
            qv  = __half2float(qkv[base]) * scale;
            kv  = __half2float(qkv[base + DIM]);
            vv_ = __half2float(qkv[base + 2*DIM]);
        }
        qsh[n*(QS2*2) + d] = __float2half_rn(qv);
        if (n < 56) kkh[n*(QS2*2) + d] = __float2half_rn(kv);
        vvh[d*(VS2*2) + n] = __float2half_rn(vv_);
    }
    {
        int win = bw % NWIN;
        int type = ((win >> 2) == 3 ? 2 : 0) + ((win & 3) == 3 ? 1 : 0);
        const float* tp = tbl + (size_t)(type*HEADS + h)*NTOK*NTOK;
        for (int i = tid; i < NTOK*NTOK; i += 128) tsm[i] = tp[i];
    }
    __syncthreads();

    int row = wid*16 + q8;

    float s[7][4];
    #pragma unroll
    for (int nf = 0; nf < 7; nf++)
        #pragma unroll
        for (int e = 0; e < 4; e++) s[nf][e] = 0.f;
    #pragma unroll
    for (int ks = 0; ks < 2; ks++) {
        int kb = ks*8;
        uint32_t af[4];
        af[0] = qs[row*QS2 + kb + c4];
        af[1] = qs[(row+8)*QS2 + kb + c4];
        af[2] = qs[row*QS2 + kb + c4 + 4];
        af[3] = qs[(row+8)*QS2 + kb + c4 + 4];
        #pragma unroll
        for (int nf = 0; nf < 7; nf++) {
            uint32_t bf[2];
            bf[0] = kkp[(nf*8 + q8)*QS2 + kb + c4];
            bf[1] = kkp[(nf*8 + q8)*QS2 + kb + c4 + 4];
            mma_f16(s[nf], af, bf);
        }
    }
    __syncthreads();   // qs/kk dead; ps may overwrite

    bool rv0 = row < NTOK, rv1 = (row+8) < NTOK;
    float mx0 = -1e30f, mx1 = -1e30f;
    #pragma unroll
    for (int nf = 0; nf < 7; nf++) {
        int col0 = nf*8 + 2*c4, col1 = col0 + 1;
        bool cv0 = col0 < NTOK, cv1 = col1 < NTOK;
        s[nf][0] = (rv0 && cv0) ? s[nf][0] + tsm[row*NTOK + col0] : -1e30f;
        s[nf][1] = (rv0 && cv1) ? s[nf][1] + tsm[row*NTOK + col1] : -1e30f;
        s[nf][2] = (rv1 && cv0) ? s[nf][2] + tsm[(row+8)*NTOK + col0] : -1e30f;
        s[nf][3] = (rv1 && cv1) ? s[nf][3] + tsm[(row+8)*NTOK + col1] : -1e30f;
        mx0 = fmaxf(mx0, fmaxf(s[nf][0], s[nf][1]));
        mx1 = fmaxf(mx1, fmaxf(s[nf][2], s[nf][3]));
    }
    mx0 = fmaxf(mx0, __shfl_xor_sync(~0u, mx0, 1));
    mx0 = fmaxf(mx0, __shfl_xor_sync(~0u, mx0, 2));
    mx1 = fmaxf(mx1, __shfl_xor_sync(~0u, mx1, 1));
    mx1 = fmaxf(mx1, __shfl_xor_sync(~0u, mx1, 2));
    float sum0 = 0.f, sum1 = 0.f;
    #pragma unroll
    for (int nf = 0; nf < 7; nf++) {
        float e0 = __expf(s[nf][0] - mx0);
        float e1 = __expf(s[nf][1] - mx0);
        float e2 = __expf(s[nf][2] - mx1);
        float e3 = __expf(s[nf][3] - mx1);
        sum0 += e0 + e1; sum1 += e2 + e3;
        __half2 p0 = __floats2half2_rn(e0, e1);
        __half2 p1 = __floats2half2_rn(e2, e3);
        ps[row*PS2 + nf*4 + c4]     = *(uint32_t*)&p0;
        ps[(row+8)*PS2 + nf*4 + c4] = *(uint32_t*)&p1;
    }
    ps[row*PS2 + 28 + c4]     = 0;
    ps[(row+8)*PS2 + 28 + c4] = 0;
    sum0 += __shfl_xor_sync(~0u, sum0, 1);
    sum0 += __shfl_xor_sync(~0u, sum0, 2);
    sum1 += __shfl_xor_sync(~0u, sum1, 1);
    sum1 += __shfl_xor_sync(~0u, sum1, 2);
    float inv0 = 1.f / sum0, inv1 = 1.f / sum1;
    __syncwarp();

    float o[4][4];
    #pragma unroll
    for (int ni = 0; ni < 4; ni++)
        #pragma unroll
        for (int e = 0; e < 4; e++) o[ni][e] = 0.f;
    #pragma unroll
    for (int ks = 0; ks < 4; ks++) {
        int kb = ks*8;
        uint32_t af[4];
        af[0] = ps[row*PS2 + kb + c4];
        af[1] = ps[(row+8)*PS2 + kb + c4];
        af[2] = ps[row*PS2 + kb + c4 + 4];
        af[3] = ps[(row+8)*PS2 + kb + c4 + 4];
        #pragma unroll
        for (int ni = 0; ni < 4; ni++) {
            uint32_t bf[2];
            bf[0] = vvT[(ni*8 + q8)*VS2 + kb + c4];
            bf[1] = vvT[(ni*8 + q8)*VS2 + kb + c4 + 4];
            mma_f16(o[ni], af, bf);
        }
    }

    #pragma unroll
    for (int ni = 0; ni < 4; ni++) {
        int d0 = ni*8 + 2*c4;
        if (rv0) {
            __half2 hv = __floats2half2_rn(o[ni][0]*inv0, o[ni][1]*inv0);
            *(__half2*)&out[(size_t)(bw*NTOK + row)*DIM + h*HD + d0] = hv;
        }
        if (rv1) {
            __half2 hv = __floats2half2_rn(o[ni][2]*inv1, o[ni][3]*inv1);
            *(__half2*)&out[(size_t)(bw*NTOK + row + 8)*DIM + h*HD + d0] = hv;
        }
    }
}

// ---------------- launcher -----------------------------------------------------
extern "C" void kernel_launch(void* const* d_in, const int* in_sizes, int n_in,
                              void* d_out, int out_size) {
    const float* x      = (const float*)d_in[0];
    const float* n1w    = (const float*)d_in[1];
    const float* n1b    = (const float*)d_in[2];
    const float* qkv_w  = (const float*)d_in[3];
    const float* qkv_b  = (const float*)d_in[4];
    const float* proj_w = (const float*)d_in[5];
    const float* proj_b = (const float*)d_in[6];
    const float* btab   = (const float*)d_in[7];
    const float* n2w    = (const float*)d_in[8];
    const float* n2b    = (const float*)d_in[9];
    const float* fc1_w  = (const float*)d_in[10];
    const float* fc1_b  = (const float*)d_in[11];
    const float* fc2_w  = (const float*)d_in[12];
    const float* fc2_b  = (const float*)d_in[13];
    float* out = (float*)d_out;

    __half *xw, *qkvb, *att, *z, *hid, *wq, *wp, *w1, *w2;
    float *x1, *tbl;
    cudaGetSymbolAddress((void**)&xw,   g_xw);
    cudaGetSymbolAddress((void**)&qkvb, g_qkv);
    cudaGetSymbolAddress((void**)&att,  g_att);
    cudaGetSymbolAddress((void**)&x1,   g_x1);
    cudaGetSymbolAddress((void**)&z,    g_z);
    cudaGetSymbolAddress((void**)&hid,  g_hid);
    cudaGetSymbolAddress((void**)&wq,   g_wq);
    cudaGetSymbolAddress((void**)&wp,   g_wp);
    cudaGetSymbolAddress((void**)&w1,   g_w1);
    cudaGetSymbolAddress((void**)&w2,   g_w2);
    cudaGetSymbolAddress((void**)&tbl,  g_tbl);

    static bool attr_done = false;
    if (!attr_done) {
        cudaFuncSetAttribute(mma_gemm<0>, cudaFuncAttributeMaxDynamicSharedMemorySize, SMEM_T);
        cudaFuncSetAttribute(mma_gemm<1>, cudaFuncAttributeMaxDynamicSharedMemorySize, SMEM_T);
        cudaFuncSetAttribute(mma_gemm<2>, cudaFuncAttributeMaxDynamicSharedMemorySize, SMEM_T);
        cudaFuncSetAttribute(mma_gemm<3>, cudaFuncAttributeMaxDynamicSharedMemorySize, SMEM_T);
        attr_done = true;
    }

    const int n0 = 3*DIM*DIM/4, n1 = DIM*DIM/4, n2 = MLPH*DIM/4, n3 = DIM*MLPH/4;
    wprep_all<<<(n0+n1+n2+n3 + 255)/256, 256>>>(qkv_w, wq, n0, proj_w, wp, n1,
                                                fc1_w, w1, n2, fc2_w, w2, n3);
    tbuild_kernel<<<48, 256>>>(btab, tbl);

    // 1. LN1 + cyclic shift + window partition (half out)
    ln_kernel<1><<<ROWS, 128>>>(x, n1w, n1b, xw);
    // 2. QKV projection (fp16, 256x128 CTA tile)
    mma_gemm<0><<<dim3((3*DIM)/128, ROWS/256), 256, SMEM_T>>>(xw, wq, qkv_b, nullptr, qkvb, ROWS, 3*DIM, DIM);
    // 3. windowed attention (fp16 tensor cores)
    attn_mma<<<dim3(BATCH*NWIN, HEADS), 128>>>(qkvb, tbl, att);
    // 4. proj + window reverse + unshift + shortcut residual (f32 out)
    mma_gemm<3><<<dim3(DIM/128, ROWS/256), 256, SMEM_T>>>(att, wp, proj_b, x, x1, ROWS, DIM, DIM);
    // 5. LN2 (half out)
    ln_kernel<0><<<ROWS, 128>>>(x1, n2w, n2b, z);
    // 6. fc1 + exact GELU (half out)
    mma_gemm<1><<<dim3(MLPH/128, ROWS/256), 256, SMEM_T>>>(z, w1, fc1_b, nullptr, hid, ROWS, MLPH, DIM);
    // 7. fc2 + residual -> final output (f32)
    mma_gemm<2><<<dim3(DIM/128, ROWS/256), 256, SMEM_T>>>(hid, w2, fc2_b, x1, out, ROWS, DIM, MLPH);
}

// round 11
// speedup vs baseline: 1.1357x; 1.1357x over previous
#include <cuda_runtime.h>
#include <cuda_fp16.h>
#include <math.h>
#include <stdint.h>

#define BATCH   64
#define HIMG    28
#define WIMG    28
#define DIM     384
#define HEADS   12
#define HD      32
#define WIN     7
#define SHIFT   3
#define NTOK    49
#define NWIN    16
#define ROWS    (BATCH*NWIN*NTOK)   // 50176
#define MLPH    1536
#define BPB     4                   // batch images per attention block

// ---------------- scratch ----------------------------------------------------
__device__ __half g_xw [ROWS*DIM];
__device__ __half g_qkv[ROWS*3*DIM];
__device__ __half g_att[ROWS*DIM];
__device__ float  g_x1 [ROWS*DIM];
__device__ __half g_z  [ROWS*DIM];
__device__ __half g_hid[(size_t)ROWS*MLPH];
// fp16 weights
__device__ __half g_wq[3*DIM*DIM];
__device__ __half g_wp[DIM*DIM];
__device__ __half g_w1[MLPH*DIM];
__device__ __half g_w2[DIM*MLPH];
// combined bias+mask table (half): [4 window types][12 heads][49][49]
__device__ __half g_tbl[48*NTOK*NTOK];

// ---------------- helpers ------------------------------------------------------
__device__ __forceinline__ uint32_t smem_u32(const void* p) {
    uint32_t a;
    asm("{ .reg .u64 t; cvta.to.shared.u64 t, %1; cvt.u32.u64 %0, t; }" : "=r"(a) : "l"(p));
    return a;
}
__device__ __forceinline__ void cp16(uint32_t s, const void* g) {
    asm volatile("cp.async.cg.shared.global [%0], [%1], 16;" :: "r"(s), "l"(g));
}
#define CP_COMMIT() asm volatile("cp.async.commit_group;" ::: "memory")
#define CP_WAIT1()  asm volatile("cp.async.wait_group 1;" ::: "memory")

__device__ __forceinline__ void mma_f16(float* d, const uint32_t* a, const uint32_t* b) {
    asm volatile(
        "mma.sync.aligned.m16n8k16.row.col.f32.f16.f16.f32 "
        "{%0,%1,%2,%3}, {%4,%5,%6,%7}, {%8,%9}, {%0,%1,%2,%3};"
        : "+f"(d[0]), "+f"(d[1]), "+f"(d[2]), "+f"(d[3])
        : "r"(a[0]), "r"(a[1]), "r"(a[2]), "r"(a[3]), "r"(b[0]), "r"(b[1]));
}
__device__ __forceinline__ void ldsm4(uint32_t& r0, uint32_t& r1, uint32_t& r2,
                                      uint32_t& r3, uint32_t addr) {
    asm volatile("ldmatrix.sync.aligned.m8n8.x4.shared.b16 {%0,%1,%2,%3}, [%4];"
        : "=r"(r0), "=r"(r1), "=r"(r2), "=r"(r3) : "r"(addr));
}

// ---------------- weight prep: fp32 -> fp16 (all 4 matrices, 1 launch) ---------
__global__ void wprep_all(const float* s0, __half* d0, int n0,
                          const float* s1, __half* d1, int n1,
                          const float* s2, __half* d2, int n2,
                          const float* s3, __half* d3, int n3) {
    int i = blockIdx.x * blockDim.x + threadIdx.x;
    const float* s; __half* d; int j = i;
    if (j < n0) { s = s0; d = d0; }
    else { j -= n0; if (j < n1) { s = s1; d = d1; }
    else { j -= n1; if (j < n2) { s = s2; d = d2; }
    else { j -= n2; if (j >= n3) return; s = s3; d = d3; } } }
    float4 v = ((const float4*)s)[j];
    __half2* dp = (__half2*)(d + j*4);
    dp[0] = __floats2half2_rn(v.x, v.y);
    dp[1] = __floats2half2_rn(v.z, v.w);
}

// ---------------- bias+mask table build (half) ----------------------------------
__global__ void tbuild_kernel(const float* __restrict__ btab, __half* __restrict__ tbl) {
    int th = blockIdx.x;
    int type = th / HEADS, h = th % HEADS;
    int eh = (type >> 1) & 1, ew = type & 1;
    for (int e = threadIdx.x; e < NTOK*NTOK; e += blockDim.x) {
        int n = e / NTOK, m = e % NTOK;
        int i1 = n/7, j1 = n%7, i2 = m/7, j2 = m%7;
        float v = btab[((i1 - i2 + 6)*13 + (j1 - j2 + 6))*HEADS + h];
        int r1 = (eh ? (i1 < 4 ? 1 : 2) : 0) * 3 + (ew ? (j1 < 4 ? 1 : 2) : 0);
        int r2 = (eh ? (i2 < 4 ? 1 : 2) : 0) * 3 + (ew ? (j2 < 4 ? 1 : 2) : 0);
        if (r1 != r2) v -= 100.f;
        tbl[th*NTOK*NTOK + e] = __float2half_rn(v);
    }
}

// ---------------- LayerNorm (optionally fused shift+window gather), half out ---
template<int GATHER>
__global__ void ln_kernel(const float* __restrict__ x, const float* __restrict__ w,
                          const float* __restrict__ b, __half* __restrict__ out) {
    int r = blockIdx.x;
    int src = r;
    if (GATHER) {
        int bb  = r / (NWIN*NTOK);
        int rem = r % (NWIN*NTOK);
        int win = rem / NTOK, n = rem % NTOK;
        int wh = win / 4, ww = win % 4;
        int i = n / 7, j = n % 7;
        int sh = (wh*7 + i + SHIFT) % HIMG;
        int sw = (ww*7 + j + SHIFT) % WIMG;
        src = bb*(HIMG*WIMG) + sh*WIMG + sw;
    }
    const float* xp = x + (size_t)src * DIM;
    int tid = threadIdx.x;
    float v0 = xp[tid], v1 = xp[tid+128], v2 = xp[tid+256];
    float s = v0 + v1 + v2;
    __shared__ float red[4];
    #pragma unroll
    for (int o = 16; o; o >>= 1) s += __shfl_xor_sync(~0u, s, o);
    if ((tid & 31) == 0) red[tid >> 5] = s;
    __syncthreads();
    float mean = (red[0]+red[1]+red[2]+red[3]) * (1.0f/DIM);
    float d0 = v0-mean, d1 = v1-mean, d2 = v2-mean;
    float q = d0*d0 + d1*d1 + d2*d2;
    #pragma unroll
    for (int o = 16; o; o >>= 1) q += __shfl_xor_sync(~0u, q, o);
    __syncthreads();
    if ((tid & 31) == 0) red[tid >> 5] = q;
    __syncthreads();
    float var = (red[0]+red[1]+red[2]+red[3]) * (1.0f/DIM);
    float inv = rsqrtf(var + 1e-5f);
    __half* op = out + (size_t)r * DIM;
    op[tid]     = __float2half_rn(d0*inv*w[tid]     + b[tid]);
    op[tid+128] = __float2half_rn(d1*inv*w[tid+128] + b[tid+128]);
    op[tid+256] = __float2half_rn(d2*inv*w[tid+256] + b[tid+256]);
}

// ---------------- pipelined fp16 GEMM, 4 warps, 64x64 warp tile, ldmatrix ------
// CTA tile 128x128, BK=64 halves (128B/row), 3-stage cp.async, 1 sync per tile.
#define SSZ 8192   // u32 per stage (A 4096 + B 4096)
template<int MODE>
__global__ void __launch_bounds__(128, 2)
mma_gemm(const __half* __restrict__ A, const __half* __restrict__ W,
         const float* __restrict__ bias, const float* __restrict__ res,
         void* __restrict__ outv, int M, int N, int K) {
    extern __shared__ __align__(16) uint32_t smem[];
    uint32_t sbase = smem_u32(smem);
    int tid  = threadIdx.x;
    int wid  = tid >> 5, lane = tid & 31;
    int wm   = wid >> 1, wn = wid & 1;           // warp grid 2x2
    int q    = lane >> 2, c = lane & 3;
    int m0   = blockIdx.y * 128, n0 = blockIdx.x * 128;

    int sr = tid >> 3;          // staging row base
    int sc = tid & 7;           // 16B chunk along k

    int lrow = (lane & 7) + ((lane >> 3) & 1) * 8;   // 0..15
    int lch  = lane >> 4;                            // 0 or 1
    int lb7  = lane & 7;

    const __half* Ag0 = A + (size_t)(m0 + sr) * K + sc*8;
    const __half* Wg0 = W + (size_t)(n0 + sr) * K + sc*8;

    float acc[4][8][4];
    #pragma unroll
    for (int i = 0; i < 4; i++)
        #pragma unroll
        for (int j = 0; j < 8; j++)
            #pragma unroll
            for (int e = 0; e < 4; e++) acc[i][j][e] = 0.f;

    const int T = K >> 6;       // BK = 64 halves

    auto load_tile = [&](int t) {
        uint32_t sb = sbase + (uint32_t)(t % 3) * (SSZ*4);
        const __half* Ag = Ag0 + t*64;
        const __half* Wg = Wg0 + t*64;
        #pragma unroll
        for (int i = 0; i < 8; i++) {
            int m = sr + i*16;
            uint32_t off = (uint32_t)(m*128 + ((sc*16) ^ ((m & 7) * 16)));
            cp16(sb + off,         Ag + (size_t)i*16*K);
            cp16(sb + 16384 + off, Wg + (size_t)i*16*K);
        }
    };

    load_tile(0); CP_COMMIT();
    load_tile(1); CP_COMMIT();

    for (int t = 0; t < T; t++) {
        CP_WAIT1();
        __syncthreads();
        if (t + 2 < T) load_tile(t + 2);
        CP_COMMIT();

        uint32_t stage = sbase + (uint32_t)(t % 3) * (SSZ*4);
        uint32_t abase = stage + (uint32_t)((wm*64 + lrow) * 128);
        uint32_t bbase = stage + 16384 + (uint32_t)((wn*64 + lrow) * 128);
        #pragma unroll
        for (int ks = 0; ks < 4; ks++) {       // 4 x k16
            uint32_t sw = (uint32_t)(((ks*2 + lch) ^ lb7) * 16);
            uint32_t af[4][4];
            #pragma unroll
            for (int mi = 0; mi < 4; mi++)
                ldsm4(af[mi][0], af[mi][1], af[mi][2], af[mi][3],
                      abase + mi*2048 + sw);
            uint32_t bf[8][2];
            #pragma unroll
            for (int nb = 0; nb < 4; nb++) {
                uint32_t r0, r1, r2, r3;
                ldsm4(r0, r1, r2, r3, bbase + nb*2048 + sw);
                bf[2*nb][0]   = r0; bf[2*nb+1][0] = r1;
                bf[2*nb][1]   = r2; bf[2*nb+1][1] = r3;
            }
            #pragma unroll
            for (int mi = 0; mi < 4; mi++)
                #pragma unroll
                for (int ni = 0; ni < 8; ni++)
                    mma_f16(acc[mi][ni], af[mi], bf[ni]);
        }
    }

    // ---- epilogue ----
    #pragma unroll
    for (int mi = 0; mi < 4; mi++) {
        int r0 = m0 + wm*64 + mi*16 + q;
        int r1 = r0 + 8;
        size_t or0, or1;
        if (MODE == 3) {
            #pragma unroll
            for (int half_ = 0; half_ < 2; half_++) {
                int m = half_ ? r1 : r0;
                int bbi = m / (NWIN*NTOK);
                int rem = m % (NWIN*NTOK);
                int win = rem / NTOK, n = rem % NTOK;
                int wh = win >> 2, ww = win & 3, ii = n / 7, jj = n % 7;
                int dh = (wh*7 + ii + SHIFT) % HIMG;
                int dw = (ww*7 + jj + SHIFT) % WIMG;
                size_t o = (size_t)bbi*(HIMG*WIMG) + dh*WIMG + dw;
                if (half_) or1 = o; else or0 = o;
            }
        } else {
            or0 = (size_t)r0; or1 = (size_t)r1;
        }
        #pragma unroll
        for (int ni = 0; ni < 8; ni++) {
            int col = n0 + wn*64 + ni*8 + 2*c;
            float2 bv = *(const float2*)&bias[col];
            float v00 = acc[mi][ni][0] + bv.x, v01 = acc[mi][ni][1] + bv.y;
            float v10 = acc[mi][ni][2] + bv.x, v11 = acc[mi][ni][3] + bv.y;
            if (MODE == 1) {
                v00 = 0.5f*v00*(1.0f + erff(v00*0.70710678118654752f));
                v01 = 0.5f*v01*(1.0f + erff(v01*0.70710678118654752f));
                v10 = 0.5f*v10*(1.0f + erff(v10*0.70710678118654752f));
                v11 = 0.5f*v11*(1.0f + erff(v11*0.70710678118654752f));
            }
            if (MODE >= 2) {
                float2 ra = *(const float2*)&res[or0*N + col];
                float2 rb = *(const float2*)&res[or1*N + col];
                v00 += ra.x; v01 += ra.y; v10 += rb.x; v11 += rb.y;
            }
            if (MODE == 0 || MODE == 1) {
                __half* O = (__half*)outv;
                *(__half2*)&O[or0*N + col] = __floats2half2_rn(v00, v01);
                *(__half2*)&O[or1*N + col] = __floats2half2_rn(v10, v11);
            } else {
                float* O = (float*)outv;
                float2 o0; o0.x = v00; o0.y = v01;
                float2 o1; o1.x = v10; o1.y = v11;
                *(float2*)&O[or0*N + col] = o0;
                *(float2*)&O[or1*N + col] = o1;
            }
        }
    }
}

// ---------------- fp16 tensor-core windowed attention, BPB batches per block ----
// grid: ((BATCH/BPB)*NWIN, HEADS). Table staged ONCE per block (half), reused.
// smem (u32): qs 64x20 | kk 56x20 | vvT 32x36 | tsm(half) 3200 entries = 1600 u32
// ps (P, half2) 64x36 aliases qs+kk after each S-phase.
#define QS2 20
#define VS2 36
#define PS2 36
__global__ void __launch_bounds__(128)
attn_mma(const __half* __restrict__ qkv, const __half* __restrict__ tbl,
         __half* __restrict__ out) {
    int win = blockIdx.x % NWIN;
    int bg  = blockIdx.x / NWIN;       // batch group 0..BATCH/BPB-1
    int h   = blockIdx.y;
    __shared__ uint32_t sm[5152];
    uint32_t* qs  = sm;                   // 1280
    uint32_t* kkp = sm + 1280;            // 1120
    uint32_t* vvT = sm + 2400;            // 1152
    __half*   tsm = (__half*)(sm + 3552); // 3200 halves (padded; idx<3136 used)
    uint32_t* ps  = sm;                   // 2304 (aliases qs+kk)
    __half* qsh = (__half*)qs;
    __half* kkh = (__half*)kkp;
    __half* vvh = (__half*)vvT;
    int tid = threadIdx.x;
    int wid = tid >> 5, lane = tid & 31;
    int q8 = lane >> 2, c4 = lane & 3;
    const float scale = 0.17677669529663689f;
    int row = wid*16 + q8;
    bool rv0 = row < NTOK, rv1 = (row+8) < NTOK;

    // stage table slab once (half)
    {
        int type = ((win >> 2) == 3 ? 2 : 0) + ((win & 3) == 3 ? 1 : 0);
        const __half* tp = tbl + (size_t)(type*HEADS + h)*NTOK*NTOK;
        for (int i = tid; i < NTOK*NTOK; i += 128) tsm[i] = tp[i];
    }

    for (int bi = 0; bi < BPB; bi++) {
        int bw = (bg*BPB + bi)*NWIN + win;
        __syncthreads();   // prior iteration's ps reads done; table staged (iter 0)

        // stage q (scaled), k, V k-packed; zeros in padding
        for (int idx = tid; idx < 64*32; idx += 128) {
            int n = idx >> 5, d = idx & 31;
            float qv = 0.f, kv = 0.f, vv_ = 0.f;
            if (n < NTOK) {
                size_t base = (size_t)(bw*NTOK + n)*(3*DIM) + h*HD + d;
                qv  = __half2float(qkv[base]) * scale;
                kv  = __half2float(qkv[base + DIM]);
                vv_ = __half2float(qkv[base + 2*DIM]);
            }
            qsh[n*(QS2*2) + d] = __float2half_rn(qv);
            if (n < 56) kkh[n*(QS2*2) + d] = __float2half_rn(kv);
            vvh[d*(VS2*2) + n] = __float2half_rn(vv_);
        }
        __syncthreads();

        // ---- S = Q @ K^T (2 x k16) ----
        float s[7][4];
        #pragma unroll
        for (int nf = 0; nf < 7; nf++)
            #pragma unroll
            for (int e = 0; e < 4; e++) s[nf][e] = 0.f;
        #pragma unroll
        for (int ks = 0; ks < 2; ks++) {
            int kb = ks*8;
            uint32_t af[4];
            af[0] = qs[row*QS2 + kb + c4];
            af[1] = qs[(row+8)*QS2 + kb + c4];
            af[2] = qs[row*QS2 + kb + c4 + 4];
            af[3] = qs[(row+8)*QS2 + kb + c4 + 4];
            #pragma unroll
            for (int nf = 0; nf < 7; nf++) {
                uint32_t bf[2];
                bf[0] = kkp[(nf*8 + q8)*QS2 + kb + c4];
                bf[1] = kkp[(nf*8 + q8)*QS2 + kb + c4 + 4];
                mma_f16(s[nf], af, bf);
            }
        }
        __syncthreads();   // qs/kk dead; ps may overwrite

        // ---- bias+mask, softmax (unnormalized P into ps as half2) ----
        float mx0 = -1e30f, mx1 = -1e30f;
        #pragma unroll
        for (int nf = 0; nf < 7; nf++) {
            int col0 = nf*8 + 2*c4, col1 = col0 + 1;
            bool cv0 = col0 < NTOK, cv1 = col1 < NTOK;
            s[nf][0] = (rv0 && cv0) ? s[nf][0] + __half2float(tsm[row*NTOK + col0]) : -1e30f;
            s[nf][1] = (rv0 && cv1) ? s[nf][1] + __half2float(tsm[row*NTOK + col1]) : -1e30f;
            s[nf][2] = (rv1 && cv0) ? s[nf][2] + __half2float(tsm[(row+8)*NTOK + col0]) : -1e30f;
            s[nf][3] = (rv1 && cv1) ? s[nf][3] + __half2float(tsm[(row+8)*NTOK + col1]) : -1e30f;
            mx0 = fmaxf(mx0, fmaxf(s[nf][0], s[nf][1]));
            mx1 = fmaxf(mx1, fmaxf(s[nf][2], s[nf][3]));
        }
        mx0 = fmaxf(mx0, __shfl_xor_sync(~0u, mx0, 1));
        mx0 = fmaxf(mx0, __shfl_xor_sync(~0u, mx0, 2));
        mx1 = fmaxf(mx1, __shfl_xor_sync(~0u, mx1, 1));
        mx1 = fmaxf(mx1, __shfl_xor_sync(~0u, mx1, 2));
        float sum0 = 0.f, sum1 = 0.f;
        #pragma unroll
        for (int nf = 0; nf < 7; nf++) {
            float e0 = __expf(s[nf][0] - mx0);
            float e1 = __expf(s[nf][1] - mx0);
            float e2 = __expf(s[nf][2] - mx1);
            float e3 = __expf(s[nf][3] - mx1);
            sum0 += e0 + e1; sum1 += e2 + e3;
            __half2 p0 = __floats2half2_rn(e0, e1);
            __half2 p1 = __floats2half2_rn(e2, e3);
            ps[row*PS2 + nf*4 + c4]     = *(uint32_t*)&p0;
            ps[(row+8)*PS2 + nf*4 + c4] = *(uint32_t*)&p1;
        }
        ps[row*PS2 + 28 + c4]     = 0;
        ps[(row+8)*PS2 + 28 + c4] = 0;
        sum0 += __shfl_xor_sync(~0u, sum0, 1);
        sum0 += __shfl_xor_sync(~0u, sum0, 2);
        sum1 += __shfl_xor_sync(~0u, sum1, 1);
        sum1 += __shfl_xor_sync(~0u, sum1, 2);
        float inv0 = 1.f / sum0, inv1 = 1.f / sum1;
        __syncwarp();      // each warp reads only the ps rows it wrote

        // ---- O = P @ V (4 x k16 over 64 padded tokens) ----
        float o[4][4];
        #pragma unroll
        for (int ni = 0; ni < 4; ni++)
            #pragma unroll
            for (int e = 0; e < 4; e++) o[ni][e] = 0.f;
        #pragma unroll
        for (int ks = 0; ks < 4; ks++) {
            int kb = ks*8;
            uint32_t af[4];
            af[0] = ps[row*PS2 + kb + c4];
            af[1] = ps[(row+8)*PS2 + kb + c4];
            af[2] = ps[row*PS2 + kb + c4 + 4];
            af[3] = ps[(row+8)*PS2 + kb + c4 + 4];
            #pragma unroll
            for (int ni = 0; ni < 4; ni++) {
                uint32_t bf[2];
                bf[0] = vvT[(ni*8 + q8)*VS2 + kb + c4];
                bf[1] = vvT[(ni*8 + q8)*VS2 + kb + c4 + 4];
                mma_f16(o[ni], af, bf);
            }
        }

        // ---- store half2 ----
        #pragma unroll
        for (int ni = 0; ni < 4; ni++) {
            int d0 = ni*8 + 2*c4;
            if (rv0) {
                __half2 hv = __floats2half2_rn(o[ni][0]*inv0, o[ni][1]*inv0);
                *(__half2*)&out[(size_t)(bw*NTOK + row)*DIM + h*HD + d0] = hv;
            }
            if (rv1) {
                __half2 hv = __floats2half2_rn(o[ni][2]*inv1, o[ni][3]*inv1);
                *(__half2*)&out[(size_t)(bw*NTOK + row + 8)*DIM + h*HD + d0] = hv;
            }
        }
    }
}

// ---------------- launcher -----------------------------------------------------
extern "C" void kernel_launch(void* const* d_in, const int* in_sizes, int n_in,
                              void* d_out, int out_size) {
    const float* x      = (const float*)d_in[0];
    const float* n1w    = (const float*)d_in[1];
    const float* n1b    = (const float*)d_in[2];
    const float* qkv_w  = (const float*)d_in[3];
    const float* qkv_b  = (const float*)d_in[4];
    const float* proj_w = (const float*)d_in[5];
    const float* proj_b = (const float*)d_in[6];
    const float* btab   = (const float*)d_in[7];
    const float* n2w    = (const float*)d_in[8];
    const float* n2b    = (const float*)d_in[9];
    const float* fc1_w  = (const float*)d_in[10];
    const float* fc1_b  = (const float*)d_in[11];
    const float* fc2_w  = (const float*)d_in[12];
    const float* fc2_b  = (const float*)d_in[13];
    float* out = (float*)d_out;

    __half *xw, *qkvb, *att, *z, *hid, *wq, *wp, *w1, *w2, *tbl;
    float *x1;
    cudaGetSymbolAddress((void**)&xw,   g_xw);
    cudaGetSymbolAddress((void**)&qkvb, g_qkv);
    cudaGetSymbolAddress((void**)&att,  g_att);
    cudaGetSymbolAddress((void**)&x1,   g_x1);
    cudaGetSymbolAddress((void**)&z,    g_z);
    cudaGetSymbolAddress((void**)&hid,  g_hid);
    cudaGetSymbolAddress((void**)&wq,   g_wq);
    cudaGetSymbolAddress((void**)&wp,   g_wp);
    cudaGetSymbolAddress((void**)&w1,   g_w1);
    cudaGetSymbolAddress((void**)&w2,   g_w2);
    cudaGetSymbolAddress((void**)&tbl,  g_tbl);

    const int SMEM = 3 * SSZ * 4;   // 98304 bytes
    static bool attr_done = false;
    if (!attr_done) {
        cudaFuncSetAttribute(mma_gemm<0>, cudaFuncAttributeMaxDynamicSharedMemorySize, SMEM);
        cudaFuncSetAttribute(mma_gemm<1>, cudaFuncAttributeMaxDynamicSharedMemorySize, SMEM);
        cudaFuncSetAttribute(mma_gemm<2>, cudaFuncAttributeMaxDynamicSharedMemorySize, SMEM);
        cudaFuncSetAttribute(mma_gemm<3>, cudaFuncAttributeMaxDynamicSharedMemorySize, SMEM);
        attr_done = true;
    }

    const int n0 = 3*DIM*DIM/4, n1 = DIM*DIM/4, n2 = MLPH*DIM/4, n3 = DIM*MLPH/4;
    wprep_all<<<(n0+n1+n2+n3 + 255)/256, 256>>>(qkv_w, wq, n0, proj_w, wp, n1,
                                                fc1_w, w1, n2, fc2_w, w2, n3);
    tbuild_kernel<<<48, 256>>>(btab, tbl);

    // 1. LN1 + cyclic shift + window partition (half out)
    ln_kernel<1><<<ROWS, 128>>>(x, n1w, n1b, xw);
    // 2. QKV projection (fp16 tensor cores, ldmatrix)
    mma_gemm<0><<<dim3((3*DIM)/128, ROWS/128), 128, SMEM>>>(xw, wq, qkv_b, nullptr, qkvb, ROWS, 3*DIM, DIM);
    // 3. windowed attention (fp16 tensor cores, 4 batches per block)
    attn_mma<<<dim3((BATCH/BPB)*NWIN, HEADS), 128>>>(qkvb, tbl, att);
    // 4. proj + window reverse + unshift + shortcut residual (f32 out)
    mma_gemm<3><<<dim3(DIM/128, ROWS/128), 128, SMEM>>>(att, wp, proj_b, x, x1, ROWS, DIM, DIM);
    // 5. LN2 (half out)
    ln_kernel<0><<<ROWS, 128>>>(x1, n2w, n2b, z);
    // 6. fc1 + exact GELU (half out)
    mma_gemm<1><<<dim3(MLPH/128, ROWS/128), 128, SMEM>>>(z, w1, fc1_b, nullptr, hid, ROWS, MLPH, DIM);
    // 7. fc2 + residual -> final output (f32)
    mma_gemm<2><<<dim3(DIM/128, ROWS/128), 128, SMEM>>>(hid, w2, fc2_b, x1, out, ROWS, DIM, MLPH);
}

// round 12
// speedup vs baseline: 1.1608x; 1.0221x over previous
#include <cuda_runtime.h>
#include <cuda_fp16.h>
#include <math.h>
#include <stdint.h>

#define BATCH   64
#define HIMG    28
#define WIMG    28
#define DIM     384
#define HEADS   12
#define HD      32
#define WIN     7
#define SHIFT   3
#define NTOK    49
#define NWIN    16
#define ROWS    (BATCH*NWIN*NTOK)   // 50176
#define MLPH    1536
#define BPB     8                   // batch images per attention block

// ---------------- scratch ----------------------------------------------------
__device__ __half g_xw [ROWS*DIM];
__device__ __half g_qkv[ROWS*3*DIM];
__device__ __half g_att[ROWS*DIM];
__device__ float  g_x1 [ROWS*DIM];
__device__ __half g_z  [ROWS*DIM];
__device__ __half g_hid[(size_t)ROWS*MLPH];
// fp16 weights
__device__ __half g_wq[3*DIM*DIM];
__device__ __half g_wp[DIM*DIM];
__device__ __half g_w1[MLPH*DIM];
__device__ __half g_w2[DIM*MLPH];
// combined bias+mask table (half): [4 window types][12 heads][49][49]
__device__ __half g_tbl[48*NTOK*NTOK];

// ---------------- helpers ------------------------------------------------------
__device__ __forceinline__ uint32_t smem_u32(const void* p) {
    uint32_t a;
    asm("{ .reg .u64 t; cvta.to.shared.u64 t, %1; cvt.u32.u64 %0, t; }" : "=r"(a) : "l"(p));
    return a;
}
__device__ __forceinline__ void cp16(uint32_t s, const void* g) {
    asm volatile("cp.async.cg.shared.global [%0], [%1], 16;" :: "r"(s), "l"(g));
}
#define CP_COMMIT() asm volatile("cp.async.commit_group;" ::: "memory")
#define CP_WAIT1()  asm volatile("cp.async.wait_group 1;" ::: "memory")

__device__ __forceinline__ void mma_f16(float* d, const uint32_t* a, const uint32_t* b) {
    asm volatile(
        "mma.sync.aligned.m16n8k16.row.col.f32.f16.f16.f32 "
        "{%0,%1,%2,%3}, {%4,%5,%6,%7}, {%8,%9}, {%0,%1,%2,%3};"
        : "+f"(d[0]), "+f"(d[1]), "+f"(d[2]), "+f"(d[3])
        : "r"(a[0]), "r"(a[1]), "r"(a[2]), "r"(a[3]), "r"(b[0]), "r"(b[1]));
}
__device__ __forceinline__ void ldsm4(uint32_t& r0, uint32_t& r1, uint32_t& r2,
                                      uint32_t& r3, uint32_t addr) {
    asm volatile("ldmatrix.sync.aligned.m8n8.x4.shared.b16 {%0,%1,%2,%3}, [%4];"
        : "=r"(r0), "=r"(r1), "=r"(r2), "=r"(r3) : "r"(addr));
}

// ---------------- weight prep: fp32 -> fp16 (all 4 matrices, 1 launch) ---------
__global__ void wprep_all(const float* s0, __half* d0, int n0,
                          const float* s1, __half* d1, int n1,
                          const float* s2, __half* d2, int n2,
                          const float* s3, __half* d3, int n3) {
    int i = blockIdx.x * blockDim.x + threadIdx.x;
    const float* s; __half* d; int j = i;
    if (j < n0) { s = s0; d = d0; }
    else { j -= n0; if (j < n1) { s = s1; d = d1; }
    else { j -= n1; if (j < n2) { s = s2; d = d2; }
    else { j -= n2; if (j >= n3) return; s = s3; d = d3; } } }
    float4 v = ((const float4*)s)[j];
    __half2* dp = (__half2*)(d + j*4);
    dp[0] = __floats2half2_rn(v.x, v.y);
    dp[1] = __floats2half2_rn(v.z, v.w);
}

// ---------------- bias+mask table build (half) ----------------------------------
__global__ void tbuild_kernel(const float* __restrict__ btab, __half* __restrict__ tbl) {
    int th = blockIdx.x;
    int type = th / HEADS, h = th % HEADS;
    int eh = (type >> 1) & 1, ew = type & 1;
    for (int e = threadIdx.x; e < NTOK*NTOK; e += blockDim.x) {
        int n = e / NTOK, m = e % NTOK;
        int i1 = n/7, j1 = n%7, i2 = m/7, j2 = m%7;
        float v = btab[((i1 - i2 + 6)*13 + (j1 - j2 + 6))*HEADS + h];
        int r1 = (eh ? (i1 < 4 ? 1 : 2) : 0) * 3 + (ew ? (j1 < 4 ? 1 : 2) : 0);
        int r2 = (eh ? (i2 < 4 ? 1 : 2) : 0) * 3 + (ew ? (j2 < 4 ? 1 : 2) : 0);
        if (r1 != r2) v -= 100.f;
        tbl[th*NTOK*NTOK + e] = __float2half_rn(v);
    }
}

// ---------------- LayerNorm: 1 warp per row, no barriers, half out -------------
// block = 128 threads = 4 warps = 4 rows; each lane: 12 floats (3 float4)
template<int GATHER>
__global__ void __launch_bounds__(128)
ln_kernel(const float* __restrict__ x, const float* __restrict__ w,
          const float* __restrict__ b, __half* __restrict__ out) {
    int r = blockIdx.x * 4 + (threadIdx.x >> 5);
    int lane = threadIdx.x & 31;
    int src = r;
    if (GATHER) {
        int bb  = r / (NWIN*NTOK);
        int rem = r % (NWIN*NTOK);
        int win = rem / NTOK, n = rem % NTOK;
        int wh = win / 4, ww = win % 4;
        int i = n / 7, j = n % 7;
        int sh = (wh*7 + i + SHIFT) % HIMG;
        int sw = (ww*7 + j + SHIFT) % WIMG;
        src = bb*(HIMG*WIMG) + sh*WIMG + sw;
    }
    const float4* xp = (const float4*)(x + (size_t)src * DIM);
    float4 v0 = xp[lane], v1 = xp[lane+32], v2 = xp[lane+64];
    float s = v0.x+v0.y+v0.z+v0.w + v1.x+v1.y+v1.z+v1.w + v2.x+v2.y+v2.z+v2.w;
    #pragma unroll
    for (int o = 16; o; o >>= 1) s += __shfl_xor_sync(~0u, s, o);
    float mean = s * (1.0f/DIM);
    float q =
        (v0.x-mean)*(v0.x-mean) + (v0.y-mean)*(v0.y-mean) +
        (v0.z-mean)*(v0.z-mean) + (v0.w-mean)*(v0.w-mean) +
        (v1.x-mean)*(v1.x-mean) + (v1.y-mean)*(v1.y-mean) +
        (v1.z-mean)*(v1.z-mean) + (v1.w-mean)*(v1.w-mean) +
        (v2.x-mean)*(v2.x-mean) + (v2.y-mean)*(v2.y-mean) +
        (v2.z-mean)*(v2.z-mean) + (v2.w-mean)*(v2.w-mean);
    #pragma unroll
    for (int o = 16; o; o >>= 1) q += __shfl_xor_sync(~0u, q, o);
    float inv = rsqrtf(q * (1.0f/DIM) + 1e-5f);
    __half* op = out + (size_t)r * DIM;
    const float4* wp4 = (const float4*)w;
    const float4* bp4 = (const float4*)b;
    #pragma unroll
    for (int i = 0; i < 3; i++) {
        float4 v = (i == 0) ? v0 : (i == 1) ? v1 : v2;
        float4 wv = wp4[lane + 32*i];
        float4 bv = bp4[lane + 32*i];
        __half2 h0 = __floats2half2_rn((v.x-mean)*inv*wv.x + bv.x,
                                       (v.y-mean)*inv*wv.y + bv.y);
        __half2 h1 = __floats2half2_rn((v.z-mean)*inv*wv.z + bv.z,
                                       (v.w-mean)*inv*wv.w + bv.w);
        __half2* o2 = (__half2*)(op + i*128 + lane*4);
        o2[0] = h0; o2[1] = h1;
    }
}

// ---------------- pipelined fp16 GEMM, 4 warps, 64x64 warp tile, ldmatrix ------
// CTA tile 128x128, BK=64 halves (128B/row), 3-stage cp.async, 1 sync per tile.
#define SSZ 8192   // u32 per stage (A 4096 + B 4096)
template<int MODE>
__global__ void __launch_bounds__(128, 2)
mma_gemm(const __half* __restrict__ A, const __half* __restrict__ W,
         const float* __restrict__ bias, const float* __restrict__ res,
         void* __restrict__ outv, int M, int N, int K) {
    extern __shared__ __align__(16) uint32_t smem[];
    uint32_t sbase = smem_u32(smem);
    int tid  = threadIdx.x;
    int wid  = tid >> 5, lane = tid & 31;
    int wm   = wid >> 1, wn = wid & 1;           // warp grid 2x2
    int q    = lane >> 2, c = lane & 3;
    int m0   = blockIdx.y * 128, n0 = blockIdx.x * 128;

    int sr = tid >> 3;          // staging row base
    int sc = tid & 7;           // 16B chunk along k

    int lrow = (lane & 7) + ((lane >> 3) & 1) * 8;   // 0..15
    int lch  = lane >> 4;                            // 0 or 1
    int lb7  = lane & 7;

    const __half* Ag0 = A + (size_t)(m0 + sr) * K + sc*8;
    const __half* Wg0 = W + (size_t)(n0 + sr) * K + sc*8;

    float acc[4][8][4];
    #pragma unroll
    for (int i = 0; i < 4; i++)
        #pragma unroll
        for (int j = 0; j < 8; j++)
            #pragma unroll
            for (int e = 0; e < 4; e++) acc[i][j][e] = 0.f;

    const int T = K >> 6;       // BK = 64 halves

    auto load_tile = [&](int t) {
        uint32_t sb = sbase + (uint32_t)(t % 3) * (SSZ*4);
        const __half* Ag = Ag0 + t*64;
        const __half* Wg = Wg0 + t*64;
        #pragma unroll
        for (int i = 0; i < 8; i++) {
            int m = sr + i*16;
            uint32_t off = (uint32_t)(m*128 + ((sc*16) ^ ((m & 7) * 16)));
            cp16(sb + off,         Ag + (size_t)i*16*K);
            cp16(sb + 16384 + off, Wg + (size_t)i*16*K);
        }
    };

    load_tile(0); CP_COMMIT();
    load_tile(1); CP_COMMIT();

    for (int t = 0; t < T; t++) {
        CP_WAIT1();
        __syncthreads();
        if (t + 2 < T) load_tile(t + 2);
        CP_COMMIT();

        uint32_t stage = sbase + (uint32_t)(t % 3) * (SSZ*4);
        uint32_t abase = stage + (uint32_t)((wm*64 + lrow) * 128);
        uint32_t bbase = stage + 16384 + (uint32_t)((wn*64 + lrow) * 128);
        #pragma unroll
        for (int ks = 0; ks < 4; ks++) {       // 4 x k16
            uint32_t sw = (uint32_t)(((ks*2 + lch) ^ lb7) * 16);
            uint32_t af[4][4];
            #pragma unroll
            for (int mi = 0; mi < 4; mi++)
                ldsm4(af[mi][0], af[mi][1], af[mi][2], af[mi][3],
                      abase + mi*2048 + sw);
            uint32_t bf[8][2];
            #pragma unroll
            for (int nb = 0; nb < 4; nb++) {
                uint32_t r0, r1, r2, r3;
                ldsm4(r0, r1, r2, r3, bbase + nb*2048 + sw);
                bf[2*nb][0]   = r0; bf[2*nb+1][0] = r1;
                bf[2*nb][1]   = r2; bf[2*nb+1][1] = r3;
            }
            #pragma unroll
            for (int mi = 0; mi < 4; mi++)
                #pragma unroll
                for (int ni = 0; ni < 8; ni++)
                    mma_f16(acc[mi][ni], af[mi], bf[ni]);
        }
    }

    // ---- epilogue ----
    #pragma unroll
    for (int mi = 0; mi < 4; mi++) {
        int r0 = m0 + wm*64 + mi*16 + q;
        int r1 = r0 + 8;
        size_t or0, or1;
        if (MODE == 3) {
            #pragma unroll
            for (int half_ = 0; half_ < 2; half_++) {
                int m = half_ ? r1 : r0;
                int bbi = m / (NWIN*NTOK);
                int rem = m % (NWIN*NTOK);
                int win = rem / NTOK, n = rem % NTOK;
                int wh = win >> 2, ww = win & 3, ii = n / 7, jj = n % 7;
                int dh = (wh*7 + ii + SHIFT) % HIMG;
                int dw = (ww*7 + jj + SHIFT) % WIMG;
                size_t o = (size_t)bbi*(HIMG*WIMG) + dh*WIMG + dw;
                if (half_) or1 = o; else or0 = o;
            }
        } else {
            or0 = (size_t)r0; or1 = (size_t)r1;
        }
        #pragma unroll
        for (int ni = 0; ni < 8; ni++) {
            int col = n0 + wn*64 + ni*8 + 2*c;
            float2 bv = *(const float2*)&bias[col];
            float v00 = acc[mi][ni][0] + bv.x, v01 = acc[mi][ni][1] + bv.y;
            float v10 = acc[mi][ni][2] + bv.x, v11 = acc[mi][ni][3] + bv.y;
            if (MODE == 1) {
                v00 = 0.5f*v00*(1.0f + erff(v00*0.70710678118654752f));
                v01 = 0.5f*v01*(1.0f + erff(v01*0.70710678118654752f));
                v10 = 0.5f*v10*(1.0f + erff(v10*0.70710678118654752f));
                v11 = 0.5f*v11*(1.0f + erff(v11*0.70710678118654752f));
            }
            if (MODE >= 2) {
                float2 ra = *(const float2*)&res[or0*N + col];
                float2 rb = *(const float2*)&res[or1*N + col];
                v00 += ra.x; v01 += ra.y; v10 += rb.x; v11 += rb.y;
            }
            if (MODE == 0 || MODE == 1) {
                __half* O = (__half*)outv;
                *(__half2*)&O[or0*N + col] = __floats2half2_rn(v00, v01);
                *(__half2*)&O[or1*N + col] = __floats2half2_rn(v10, v11);
            } else {
                float* O = (float*)outv;
                float2 o0; o0.x = v00; o0.y = v01;
                float2 o1; o1.x = v10; o1.y = v11;
                *(float2*)&O[or0*N + col] = o0;
                *(float2*)&O[or1*N + col] = o1;
            }
        }
    }
}

// ---------------- fp16 tensor-core windowed attention, BPB batches per block ----
#define QS2 20
#define VS2 36
#define PS2 36
__global__ void __launch_bounds__(128)
attn_mma(const __half* __restrict__ qkv, const __half* __restrict__ tbl,
         __half* __restrict__ out) {
    int win = blockIdx.x % NWIN;
    int bg  = blockIdx.x / NWIN;       // batch group
    int h   = blockIdx.y;
    __shared__ uint32_t sm[5152];
    uint32_t* qs  = sm;                   // 1280
    uint32_t* kkp = sm + 1280;            // 1120
    uint32_t* vvT = sm + 2400;            // 1152
    __half*   tsm = (__half*)(sm + 3552); // 3200 halves
    uint32_t* ps  = sm;                   // 2304 (aliases qs+kk)
    __half* qsh = (__half*)qs;
    __half* kkh = (__half*)kkp;
    __half* vvh = (__half*)vvT;
    int tid = threadIdx.x;
    int wid = tid >> 5, lane = tid & 31;
    int q8 = lane >> 2, c4 = lane & 3;
    const float scale = 0.17677669529663689f;
    int row = wid*16 + q8;
    bool rv0 = row < NTOK, rv1 = (row+8) < NTOK;

    // stage table slab once (half)
    {
        int type = ((win >> 2) == 3 ? 2 : 0) + ((win & 3) == 3 ? 1 : 0);
        const __half* tp = tbl + (size_t)(type*HEADS + h)*NTOK*NTOK;
        for (int i = tid; i < NTOK*NTOK; i += 128) tsm[i] = tp[i];
    }

    for (int bi = 0; bi < BPB; bi++) {
        int bw = (bg*BPB + bi)*NWIN + win;
        __syncthreads();

        for (int idx = tid; idx < 64*32; idx += 128) {
            int n = idx >> 5, d = idx & 31;
            float qv = 0.f, kv = 0.f, vv_ = 0.f;
            if (n < NTOK) {
                size_t base = (size_t)(bw*NTOK + n)*(3*DIM) + h*HD + d;
                qv  = __half2float(qkv[base]) * scale;
                kv  = __half2float(qkv[base + DIM]);
                vv_ = __half2float(qkv[base + 2*DIM]);
            }
            qsh[n*(QS2*2) + d] = __float2half_rn(qv);
            if (n < 56) kkh[n*(QS2*2) + d] = __float2half_rn(kv);
            vvh[d*(VS2*2) + n] = __float2half_rn(vv_);
        }
        __syncthreads();

        // ---- S = Q @ K^T ----
        float s[7][4];
        #pragma unroll
        for (int nf = 0; nf < 7; nf++)
            #pragma unroll
            for (int e = 0; e < 4; e++) s[nf][e] = 0.f;
        #pragma unroll
        for (int ks = 0; ks < 2; ks++) {
            int kb = ks*8;
            uint32_t af[4];
            af[0] = qs[row*QS2 + kb + c4];
            af[1] = qs[(row+8)*QS2 + kb + c4];
            af[2] = qs[row*QS2 + kb + c4 + 4];
            af[3] = qs[(row+8)*QS2 + kb + c4 + 4];
            #pragma unroll
            for (int nf = 0; nf < 7; nf++) {
                uint32_t bf[2];
                bf[0] = kkp[(nf*8 + q8)*QS2 + kb + c4];
                bf[1] = kkp[(nf*8 + q8)*QS2 + kb + c4 + 4];
                mma_f16(s[nf], af, bf);
            }
        }
        __syncthreads();   // qs/kk dead; ps may overwrite

        // ---- bias+mask, softmax ----
        float mx0 = -1e30f, mx1 = -1e30f;
        #pragma unroll
        for (int nf = 0; nf < 7; nf++) {
            int col0 = nf*8 + 2*c4, col1 = col0 + 1;
            bool cv0 = col0 < NTOK, cv1 = col1 < NTOK;
            s[nf][0] = (rv0 && cv0) ? s[nf][0] + __half2float(tsm[row*NTOK + col0]) : -1e30f;
            s[nf][1] = (rv0 && cv1) ? s[nf][1] + __half2float(tsm[row*NTOK + col1]) : -1e30f;
            s[nf][2] = (rv1 && cv0) ? s[nf][2] + __half2float(tsm[(row+8)*NTOK + col0]) : -1e30f;
            s[nf][3] = (rv1 && cv1) ? s[nf][3] + __half2float(tsm[(row+8)*NTOK + col1]) : -1e30f;
            mx0 = fmaxf(mx0, fmaxf(s[nf][0], s[nf][1]));
            mx1 = fmaxf(mx1, fmaxf(s[nf][2], s[nf][3]));
        }
        mx0 = fmaxf(mx0, __shfl_xor_sync(~0u, mx0, 1));
        mx0 = fmaxf(mx0, __shfl_xor_sync(~0u, mx0, 2));
        mx1 = fmaxf(mx1, __shfl_xor_sync(~0u, mx1, 1));
        mx1 = fmaxf(mx1, __shfl_xor_sync(~0u, mx1, 2));
        float sum0 = 0.f, sum1 = 0.f;
        #pragma unroll
        for (int nf = 0; nf < 7; nf++) {
            float e0 = __expf(s[nf][0] - mx0);
            float e1 = __expf(s[nf][1] - mx0);
            float e2 = __expf(s[nf][2] - mx1);
            float e3 = __expf(s[nf][3] - mx1);
            sum0 += e0 + e1; sum1 += e2 + e3;
            __half2 p0 = __floats2half2_rn(e0, e1);
            __half2 p1 = __floats2half2_rn(e2, e3);
            ps[row*PS2 + nf*4 + c4]     = *(uint32_t*)&p0;
            ps[(row+8)*PS2 + nf*4 + c4] = *(uint32_t*)&p1;
        }
        ps[row*PS2 + 28 + c4]     = 0;
        ps[(row+8)*PS2 + 28 + c4] = 0;
        sum0 += __shfl_xor_sync(~0u, sum0, 1);
        sum0 += __shfl_xor_sync(~0u, sum0, 2);
        sum1 += __shfl_xor_sync(~0u, sum1, 1);
        sum1 += __shfl_xor_sync(~0u, sum1, 2);
        float inv0 = 1.f / sum0, inv1 = 1.f / sum1;
        __syncwarp();

        // ---- O = P @ V ----
        float o[4][4];
        #pragma unroll
        for (int ni = 0; ni < 4; ni++)
            #pragma unroll
            for (int e = 0; e < 4; e++) o[ni][e] = 0.f;
        #pragma unroll
        for (int ks = 0; ks < 4; ks++) {
            int kb = ks*8;
            uint32_t af[4];
            af[0] = ps[row*PS2 + kb + c4];
            af[1] = ps[(row+8)*PS2 + kb + c4];
            af[2] = ps[row*PS2 + kb + c4 + 4];
            af[3] = ps[(row+8)*PS2 + kb + c4 + 4];
            #pragma unroll
            for (int ni = 0; ni < 4; ni++) {
                uint32_t bf[2];
                bf[0] = vvT[(ni*8 + q8)*VS2 + kb + c4];
                bf[1] = vvT[(ni*8 + q8)*VS2 + kb + c4 + 4];
                mma_f16(o[ni], af, bf);
            }
        }

        // ---- store half2 ----
        #pragma unroll
        for (int ni = 0; ni < 4; ni++) {
            int d0 = ni*8 + 2*c4;
            if (rv0) {
                __half2 hv = __floats2half2_rn(o[ni][0]*inv0, o[ni][1]*inv0);
                *(__half2*)&out[(size_t)(bw*NTOK + row)*DIM + h*HD + d0] = hv;
            }
            if (rv1) {
                __half2 hv = __floats2half2_rn(o[ni][2]*inv1, o[ni][3]*inv1);
                *(__half2*)&out[(size_t)(bw*NTOK + row + 8)*DIM + h*HD + d0] = hv;
            }
        }
    }
}

// ---------------- launcher -----------------------------------------------------
extern "C" void kernel_launch(void* const* d_in, const int* in_sizes, int n_in,
                              void* d_out, int out_size) {
    const float* x      = (const float*)d_in[0];
    const float* n1w    = (const float*)d_in[1];
    const float* n1b    = (const float*)d_in[2];
    const float* qkv_w  = (const float*)d_in[3];
    const float* qkv_b  = (const float*)d_in[4];
    const float* proj_w = (const float*)d_in[5];
    const float* proj_b = (const float*)d_in[6];
    const float* btab   = (const float*)d_in[7];
    const float* n2w    = (const float*)d_in[8];
    const float* n2b    = (const float*)d_in[9];
    const float* fc1_w  = (const float*)d_in[10];
    const float* fc1_b  = (const float*)d_in[11];
    const float* fc2_w  = (const float*)d_in[12];
    const float* fc2_b  = (const float*)d_in[13];
    float* out = (float*)d_out;

    __half *xw, *qkvb, *att, *z, *hid, *wq, *wp, *w1, *w2, *tbl;
    float *x1;
    cudaGetSymbolAddress((void**)&xw,   g_xw);
    cudaGetSymbolAddress((void**)&qkvb, g_qkv);
    cudaGetSymbolAddress((void**)&att,  g_att);
    cudaGetSymbolAddress((void**)&x1,   g_x1);
    cudaGetSymbolAddress((void**)&z,    g_z);
    cudaGetSymbolAddress((void**)&hid,  g_hid);
    cudaGetSymbolAddress((void**)&wq,   g_wq);
    cudaGetSymbolAddress((void**)&wp,   g_wp);
    cudaGetSymbolAddress((void**)&w1,   g_w1);
    cudaGetSymbolAddress((void**)&w2,   g_w2);
    cudaGetSymbolAddress((void**)&tbl,  g_tbl);

    const int SMEM = 3 * SSZ * 4;   // 98304 bytes
    static bool attr_done = false;
    if (!attr_done) {
        cudaFuncSetAttribute(mma_gemm<0>, cudaFuncAttributeMaxDynamicSharedMemorySize, SMEM);
        cudaFuncSetAttribute(mma_gemm<1>, cudaFuncAttributeMaxDynamicSharedMemorySize, SMEM);
        cudaFuncSetAttribute(mma_gemm<2>, cudaFuncAttributeMaxDynamicSharedMemorySize, SMEM);
        cudaFuncSetAttribute(mma_gemm<3>, cudaFuncAttributeMaxDynamicSharedMemorySize, SMEM);
        attr_done = true;
    }

    const int n0 = 3*DIM*DIM/4, n1 = DIM*DIM/4, n2 = MLPH*DIM/4, n3 = DIM*MLPH/4;
    wprep_all<<<(n0+n1+n2+n3 + 255)/256, 256>>>(qkv_w, wq, n0, proj_w, wp, n1,
                                                fc1_w, w1, n2, fc2_w, w2, n3);
    tbuild_kernel<<<48, 256>>>(btab, tbl);

    // 1. LN1 + cyclic shift + window partition (half out, warp-per-row)
    ln_kernel<1><<<ROWS/4, 128>>>(x, n1w, n1b, xw);
    // 2. QKV projection (fp16 tensor cores, ldmatrix)
    mma_gemm<0><<<dim3((3*DIM)/128, ROWS/128), 128, SMEM>>>(xw, wq, qkv_b, nullptr, qkvb, ROWS, 3*DIM, DIM);
    // 3. windowed attention (fp16 tensor cores, 8 batches per block)
    attn_mma<<<dim3((BATCH/BPB)*NWIN, HEADS), 128>>>(qkvb, tbl, att);
    // 4. proj + window reverse + unshift + shortcut residual (f32 out)
    mma_gemm<3><<<dim3(DIM/128, ROWS/128), 128, SMEM>>>(att, wp, proj_b, x, x1, ROWS, DIM, DIM);
    // 5. LN2 (half out, warp-per-row)
    ln_kernel<0><<<ROWS/4, 128>>>(x1, n2w, n2b, z);
    // 6. fc1 + exact GELU (half out)
    mma_gemm<1><<<dim3(MLPH/128, ROWS/128), 128, SMEM>>>(z, w1, fc1_b, nullptr, hid, ROWS, MLPH, DIM);
    // 7. fc2 + residual -> final output (f32)
    mma_gemm<2><<<dim3(DIM/128, ROWS/128), 128, SMEM>>>(hid, w2, fc2_b, x1, out, ROWS, DIM, MLPH);
}

// round 13
// speedup vs baseline: 1.1616x; 1.0007x over previous
#include <cuda_runtime.h>
#include <cuda_fp16.h>
#include <math.h>
#include <stdint.h>

#define BATCH   64
#define HIMG    28
#define WIMG    28
#define DIM     384
#define HEADS   12
#define HD      32
#define WIN     7
#define SHIFT   3
#define NTOK    49
#define NWIN    16
#define ROWS    (BATCH*NWIN*NTOK)   // 50176
#define MLPH    1536
#define BPB     8                   // batch images per attention block

// ---------------- scratch ----------------------------------------------------
__device__ __half g_xw [ROWS*DIM];
__device__ __half g_qkv[ROWS*3*DIM];
__device__ __half g_att[ROWS*DIM];
__device__ float  g_x1 [ROWS*DIM];
__device__ __half g_z  [ROWS*DIM];
__device__ __half g_hid[(size_t)ROWS*MLPH];
// fp16 weights
__device__ __half g_wq[3*DIM*DIM];
__device__ __half g_wp[DIM*DIM];
__device__ __half g_w1[MLPH*DIM];
__device__ __half g_w2[DIM*MLPH];
// combined bias+mask table (half): [4 window types][12 heads][49][49]
__device__ __half g_tbl[48*NTOK*NTOK];

// ---------------- helpers ------------------------------------------------------
__device__ __forceinline__ uint32_t smem_u32(const void* p) {
    uint32_t a;
    asm("{ .reg .u64 t; cvta.to.shared.u64 t, %1; cvt.u32.u64 %0, t; }" : "=r"(a) : "l"(p));
    return a;
}
__device__ __forceinline__ void cp16(uint32_t s, const void* g) {
    asm volatile("cp.async.cg.shared.global [%0], [%1], 16;" :: "r"(s), "l"(g));
}
#define CP_COMMIT() asm volatile("cp.async.commit_group;" ::: "memory")
#define CP_WAIT1()  asm volatile("cp.async.wait_group 1;" ::: "memory")

__device__ __forceinline__ void mma_f16(float* d, const uint32_t* a, const uint32_t* b) {
    asm volatile(
        "mma.sync.aligned.m16n8k16.row.col.f32.f16.f16.f32 "
        "{%0,%1,%2,%3}, {%4,%5,%6,%7}, {%8,%9}, {%0,%1,%2,%3};"
        : "+f"(d[0]), "+f"(d[1]), "+f"(d[2]), "+f"(d[3])
        : "r"(a[0]), "r"(a[1]), "r"(a[2]), "r"(a[3]), "r"(b[0]), "r"(b[1]));
}
__device__ __forceinline__ void ldsm4(uint32_t& r0, uint32_t& r1, uint32_t& r2,
                                      uint32_t& r3, uint32_t addr) {
    asm volatile("ldmatrix.sync.aligned.m8n8.x4.shared.b16 {%0,%1,%2,%3}, [%4];"
        : "=r"(r0), "=r"(r1), "=r"(r2), "=r"(r3) : "r"(addr));
}

// ---------------- weight prep: fp32 -> fp16 (all 4 matrices, 1 launch) ---------
__global__ void wprep_all(const float* s0, __half* d0, int n0,
                          const float* s1, __half* d1, int n1,
                          const float* s2, __half* d2, int n2,
                          const float* s3, __half* d3, int n3) {
    int i = blockIdx.x * blockDim.x + threadIdx.x;
    const float* s; __half* d; int j = i;
    if (j < n0) { s = s0; d = d0; }
    else { j -= n0; if (j < n1) { s = s1; d = d1; }
    else { j -= n1; if (j < n2) { s = s2; d = d2; }
    else { j -= n2; if (j >= n3) return; s = s3; d = d3; } } }
    float4 v = ((const float4*)s)[j];
    __half2* dp = (__half2*)(d + j*4);
    dp[0] = __floats2half2_rn(v.x, v.y);
    dp[1] = __floats2half2_rn(v.z, v.w);
}

// ---------------- bias+mask table build (half) ----------------------------------
__global__ void tbuild_kernel(const float* __restrict__ btab, __half* __restrict__ tbl) {
    int th = blockIdx.x;
    int type = th / HEADS, h = th % HEADS;
    int eh = (type >> 1) & 1, ew = type & 1;
    for (int e = threadIdx.x; e < NTOK*NTOK; e += blockDim.x) {
        int n = e / NTOK, m = e % NTOK;
        int i1 = n/7, j1 = n%7, i2 = m/7, j2 = m%7;
        float v = btab[((i1 - i2 + 6)*13 + (j1 - j2 + 6))*HEADS + h];
        int r1 = (eh ? (i1 < 4 ? 1 : 2) : 0) * 3 + (ew ? (j1 < 4 ? 1 : 2) : 0);
        int r2 = (eh ? (i2 < 4 ? 1 : 2) : 0) * 3 + (ew ? (j2 < 4 ? 1 : 2) : 0);
        if (r1 != r2) v -= 100.f;
        tbl[th*NTOK*NTOK + e] = __float2half_rn(v);
    }
}

// ---------------- LayerNorm: 1 warp per row, no barriers, half out -------------
// block = 128 threads = 4 warps = 4 rows; each lane: 12 floats (3 float4)
template<int GATHER>
__global__ void __launch_bounds__(128)
ln_kernel(const float* __restrict__ x, const float* __restrict__ w,
          const float* __restrict__ b, __half* __restrict__ out) {
    int r = blockIdx.x * 4 + (threadIdx.x >> 5);
    int lane = threadIdx.x & 31;
    int src = r;
    if (GATHER) {
        int bb  = r / (NWIN*NTOK);
        int rem = r % (NWIN*NTOK);
        int win = rem / NTOK, n = rem % NTOK;
        int wh = win / 4, ww = win % 4;
        int i = n / 7, j = n % 7;
        int sh = (wh*7 + i + SHIFT) % HIMG;
        int sw = (ww*7 + j + SHIFT) % WIMG;
        src = bb*(HIMG*WIMG) + sh*WIMG + sw;
    }
    const float4* xp = (const float4*)(x + (size_t)src * DIM);
    float4 v0 = xp[lane], v1 = xp[lane+32], v2 = xp[lane+64];
    float s = v0.x+v0.y+v0.z+v0.w + v1.x+v1.y+v1.z+v1.w + v2.x+v2.y+v2.z+v2.w;
    #pragma unroll
    for (int o = 16; o; o >>= 1) s += __shfl_xor_sync(~0u, s, o);
    float mean = s * (1.0f/DIM);
    float q =
        (v0.x-mean)*(v0.x-mean) + (v0.y-mean)*(v0.y-mean) +
        (v0.z-mean)*(v0.z-mean) + (v0.w-mean)*(v0.w-mean) +
        (v1.x-mean)*(v1.x-mean) + (v1.y-mean)*(v1.y-mean) +
        (v1.z-mean)*(v1.z-mean) + (v1.w-mean)*(v1.w-mean) +
        (v2.x-mean)*(v2.x-mean) + (v2.y-mean)*(v2.y-mean) +
        (v2.z-mean)*(v2.z-mean) + (v2.w-mean)*(v2.w-mean);
    #pragma unroll
    for (int o = 16; o; o >>= 1) q += __shfl_xor_sync(~0u, q, o);
    float inv = rsqrtf(q * (1.0f/DIM) + 1e-5f);
    __half* op = out + (size_t)r * DIM;
    const float4* wp4 = (const float4*)w;
    const float4* bp4 = (const float4*)b;
    #pragma unroll
    for (int i = 0; i < 3; i++) {
        float4 v = (i == 0) ? v0 : (i == 1) ? v1 : v2;
        float4 wv = wp4[lane + 32*i];
        float4 bv = bp4[lane + 32*i];
        __half2 h0 = __floats2half2_rn((v.x-mean)*inv*wv.x + bv.x,
                                       (v.y-mean)*inv*wv.y + bv.y);
        __half2 h1 = __floats2half2_rn((v.z-mean)*inv*wv.z + bv.z,
                                       (v.w-mean)*inv*wv.w + bv.w);
        __half2* o2 = (__half2*)(op + i*128 + lane*4);
        o2[0] = h0; o2[1] = h1;
    }
}

// ---------------- pipelined fp16 GEMM, 4 warps, 64x64 warp tile, ldmatrix ------
// CTA tile 128x128, BK=64 halves (128B/row), 3-stage cp.async, 1 sync per tile.
#define SSZ 8192   // u32 per stage (A 4096 + B 4096)
template<int MODE>
__global__ void __launch_bounds__(128, 2)
mma_gemm(const __half* __restrict__ A, const __half* __restrict__ W,
         const float* __restrict__ bias, const float* __restrict__ res,
         void* __restrict__ outv, int M, int N, int K) {
    extern __shared__ __align__(16) uint32_t smem[];
    uint32_t sbase = smem_u32(smem);
    int tid  = threadIdx.x;
    int wid  = tid >> 5, lane = tid & 31;
    int wm   = wid >> 1, wn = wid & 1;           // warp grid 2x2
    int q    = lane >> 2, c = lane & 3;
    int m0   = blockIdx.y * 128, n0 = blockIdx.x * 128;

    int sr = tid >> 3;          // staging row base
    int sc = tid & 7;           // 16B chunk along k

    int lrow = (lane & 7) + ((lane >> 3) & 1) * 8;   // 0..15
    int lch  = lane >> 4;                            // 0 or 1
    int lb7  = lane & 7;

    const __half* Ag0 = A + (size_t)(m0 + sr) * K + sc*8;
    const __half* Wg0 = W + (size_t)(n0 + sr) * K + sc*8;

    float acc[4][8][4];
    #pragma unroll
    for (int i = 0; i < 4; i++)
        #pragma unroll
        for (int j = 0; j < 8; j++)
            #pragma unroll
            for (int e = 0; e < 4; e++) acc[i][j][e] = 0.f;

    const int T = K >> 6;       // BK = 64 halves

    auto load_tile = [&](int t) {
        uint32_t sb = sbase + (uint32_t)(t % 3) * (SSZ*4);
        const __half* Ag = Ag0 + t*64;
        const __half* Wg = Wg0 + t*64;
        #pragma unroll
        for (int i = 0; i < 8; i++) {
            int m = sr + i*16;
            uint32_t off = (uint32_t)(m*128 + ((sc*16) ^ ((m & 7) * 16)));
            cp16(sb + off,         Ag + (size_t)i*16*K);
            cp16(sb + 16384 + off, Wg + (size_t)i*16*K);
        }
    };

    load_tile(0); CP_COMMIT();
    load_tile(1); CP_COMMIT();

    for (int t = 0; t < T; t++) {
        CP_WAIT1();
        __syncthreads();
        if (t + 2 < T) load_tile(t + 2);
        CP_COMMIT();

        uint32_t stage = sbase + (uint32_t)(t % 3) * (SSZ*4);
        uint32_t abase = stage + (uint32_t)((wm*64 + lrow) * 128);
        uint32_t bbase = stage + 16384 + (uint32_t)((wn*64 + lrow) * 128);
        #pragma unroll
        for (int ks = 0; ks < 4; ks++) {       // 4 x k16
            uint32_t sw = (uint32_t)(((ks*2 + lch) ^ lb7) * 16);
            uint32_t af[4][4];
            #pragma unroll
            for (int mi = 0; mi < 4; mi++)
                ldsm4(af[mi][0], af[mi][1], af[mi][2], af[mi][3],
                      abase + mi*2048 + sw);
            uint32_t bf[8][2];
            #pragma unroll
            for (int nb = 0; nb < 4; nb++) {
                uint32_t r0, r1, r2, r3;
                ldsm4(r0, r1, r2, r3, bbase + nb*2048 + sw);
                bf[2*nb][0]   = r0; bf[2*nb+1][0] = r1;
                bf[2*nb][1]   = r2; bf[2*nb+1][1] = r3;
            }
            #pragma unroll
            for (int mi = 0; mi < 4; mi++)
                #pragma unroll
                for (int ni = 0; ni < 8; ni++)
                    mma_f16(acc[mi][ni], af[mi], bf[ni]);
        }
    }

    // ---- epilogue ----
    #pragma unroll
    for (int mi = 0; mi < 4; mi++) {
        int r0 = m0 + wm*64 + mi*16 + q;
        int r1 = r0 + 8;
        size_t or0, or1;
        if (MODE == 3) {
            #pragma unroll
            for (int half_ = 0; half_ < 2; half_++) {
                int m = half_ ? r1 : r0;
                int bbi = m / (NWIN*NTOK);
                int rem = m % (NWIN*NTOK);
                int win = rem / NTOK, n = rem % NTOK;
                int wh = win >> 2, ww = win & 3, ii = n / 7, jj = n % 7;
                int dh = (wh*7 + ii + SHIFT) % HIMG;
                int dw = (ww*7 + jj + SHIFT) % WIMG;
                size_t o = (size_t)bbi*(HIMG*WIMG) + dh*WIMG + dw;
                if (half_) or1 = o; else or0 = o;
            }
        } else {
            or0 = (size_t)r0; or1 = (size_t)r1;
        }
        #pragma unroll
        for (int ni = 0; ni < 8; ni++) {
            int col = n0 + wn*64 + ni*8 + 2*c;
            float2 bv = *(const float2*)&bias[col];
            float v00 = acc[mi][ni][0] + bv.x, v01 = acc[mi][ni][1] + bv.y;
            float v10 = acc[mi][ni][2] + bv.x, v11 = acc[mi][ni][3] + bv.y;
            if (MODE == 1) {
                v00 = 0.5f*v00*(1.0f + erff(v00*0.70710678118654752f));
                v01 = 0.5f*v01*(1.0f + erff(v01*0.70710678118654752f));
                v10 = 0.5f*v10*(1.0f + erff(v10*0.70710678118654752f));
                v11 = 0.5f*v11*(1.0f + erff(v11*0.70710678118654752f));
            }
            if (MODE >= 2) {
                float2 ra = *(const float2*)&res[or0*N + col];
                float2 rb = *(const float2*)&res[or1*N + col];
                v00 += ra.x; v01 += ra.y; v10 += rb.x; v11 += rb.y;
            }
            if (MODE == 0 || MODE == 1) {
                __half* O = (__half*)outv;
                *(__half2*)&O[or0*N + col] = __floats2half2_rn(v00, v01);
                *(__half2*)&O[or1*N + col] = __floats2half2_rn(v10, v11);
            } else {
                float* O = (float*)outv;
                float2 o0; o0.x = v00; o0.y = v01;
                float2 o1; o1.x = v10; o1.y = v11;
                *(float2*)&O[or0*N + col] = o0;
                *(float2*)&O[or1*N + col] = o1;
            }
        }
    }
}

// ---------------- fp16 tensor-core windowed attention, BPB batches per block ----
#define QS2 20
#define VS2 36
#define PS2 36
__global__ void __launch_bounds__(128)
attn_mma(const __half* __restrict__ qkv, const __half* __restrict__ tbl,
         __half* __restrict__ out) {
    int win = blockIdx.x % NWIN;
    int bg  = blockIdx.x / NWIN;       // batch group
    int h   = blockIdx.y;
    __shared__ uint32_t sm[5152];
    uint32_t* qs  = sm;                   // 1280
    uint32_t* kkp = sm + 1280;            // 1120
    uint32_t* vvT = sm + 2400;            // 1152
    __half*   tsm = (__half*)(sm + 3552); // 3200 halves
    uint32_t* ps  = sm;                   // 2304 (aliases qs+kk)
    __half* qsh = (__half*)qs;
    __half* kkh = (__half*)kkp;
    __half* vvh = (__half*)vvT;
    int tid = threadIdx.x;
    int wid = tid >> 5, lane = tid & 31;
    int q8 = lane >> 2, c4 = lane & 3;
    const float scale = 0.17677669529663689f;
    int row = wid*16 + q8;
    bool rv0 = row < NTOK, rv1 = (row+8) < NTOK;

    // stage table slab once (half)
    {
        int type = ((win >> 2) == 3 ? 2 : 0) + ((win & 3) == 3 ? 1 : 0);
        const __half* tp = tbl + (size_t)(type*HEADS + h)*NTOK*NTOK;
        for (int i = tid; i < NTOK*NTOK; i += 128) tsm[i] = tp[i];
    }

    for (int bi = 0; bi < BPB; bi++) {
        int bw = (bg*BPB + bi)*NWIN + win;
        __syncthreads();

        for (int idx = tid; idx < 64*32; idx += 128) {
            int n = idx >> 5, d = idx & 31;
            float qv = 0.f, kv = 0.f, vv_ = 0.f;
            if (n < NTOK) {
                size_t base = (size_t)(bw*NTOK + n)*(3*DIM) + h*HD + d;
                qv  = __half2float(qkv[base]) * scale;
                kv  = __half2float(qkv[base + DIM]);
                vv_ = __half2float(qkv[base + 2*DIM]);
            }
            qsh[n*(QS2*2) + d] = __float2half_rn(qv);
            if (n < 56) kkh[n*(QS2*2) + d] = __float2half_rn(kv);
            vvh[d*(VS2*2) + n] = __float2half_rn(vv_);
        }
        __syncthreads();

        // ---- S = Q @ K^T ----
        float s[7][4];
        #pragma unroll
        for (int nf = 0; nf < 7; nf++)
            #pragma unroll
            for (int e = 0; e < 4; e++) s[nf][e] = 0.f;
        #pragma unroll
        for (int ks = 0; ks < 2; ks++) {
            int kb = ks*8;
            uint32_t af[4];
            af[0] = qs[row*QS2 + kb + c4];
            af[1] = qs[(row+8)*QS2 + kb + c4];
            af[2] = qs[row*QS2 + kb + c4 + 4];
            af[3] = qs[(row+8)*QS2 + kb + c4 + 4];
            #pragma unroll
            for (int nf = 0; nf < 7; nf++) {
                uint32_t bf[2];
                bf[0] = kkp[(nf*8 + q8)*QS2 + kb + c4];
                bf[1] = kkp[(nf*8 + q8)*QS2 + kb + c4 + 4];
                mma_f16(s[nf], af, bf);
            }
        }
        __syncthreads();   // qs/kk dead; ps may overwrite

        // ---- bias+mask, softmax ----
        float mx0 = -1e30f, mx1 = -1e30f;
        #pragma unroll
        for (int nf = 0; nf < 7; nf++) {
            int col0 = nf*8 + 2*c4, col1 = col0 + 1;
            bool cv0 = col0 < NTOK, cv1 = col1 < NTOK;
            s[nf][0] = (rv0 && cv0) ? s[nf][0] + __half2float(tsm[row*NTOK + col0]) : -1e30f;
            s[nf][1] = (rv0 && cv1) ? s[nf][1] + __half2float(tsm[row*NTOK + col1]) : -1e30f;
            s[nf][2] = (rv1 && cv0) ? s[nf][2] + __half2float(tsm[(row+8)*NTOK + col0]) : -1e30f;
            s[nf][3] = (rv1 && cv1) ? s[nf][3] + __half2float(tsm[(row+8)*NTOK + col1]) : -1e30f;
            mx0 = fmaxf(mx0, fmaxf(s[nf][0], s[nf][1]));
            mx1 = fmaxf(mx1, fmaxf(s[nf][2], s[nf][3]));
        }
        mx0 = fmaxf(mx0, __shfl_xor_sync(~0u, mx0, 1));
        mx0 = fmaxf(mx0, __shfl_xor_sync(~0u, mx0, 2));
        mx1 = fmaxf(mx1, __shfl_xor_sync(~0u, mx1, 1));
        mx1 = fmaxf(mx1, __shfl_xor_sync(~0u, mx1, 2));
        float sum0 = 0.f, sum1 = 0.f;
        #pragma unroll
        for (int nf = 0; nf < 7; nf++) {
            float e0 = __expf(s[nf][0] - mx0);
            float e1 = __expf(s[nf][1] - mx0);
            float e2 = __expf(s[nf][2] - mx1);
            float e3 = __expf(s[nf][3] - mx1);
            sum0 += e0 + e1; sum1 += e2 + e3;
            __half2 p0 = __floats2half2_rn(e0, e1);
            __half2 p1 = __floats2half2_rn(e2, e3);
            ps[row*PS2 + nf*4 + c4]     = *(uint32_t*)&p0;
            ps[(row+8)*PS2 + nf*4 + c4] = *(uint32_t*)&p1;
        }
        ps[row*PS2 + 28 + c4]     = 0;
        ps[(row+8)*PS2 + 28 + c4] = 0;
        sum0 += __shfl_xor_sync(~0u, sum0, 1);
        sum0 += __shfl_xor_sync(~0u, sum0, 2);
        sum1 += __shfl_xor_sync(~0u, sum1, 1);
        sum1 += __shfl_xor_sync(~0u, sum1, 2);
        float inv0 = 1.f / sum0, inv1 = 1.f / sum1;
        __syncwarp();

        // ---- O = P @ V ----
        float o[4][4];
        #pragma unroll
        for (int ni = 0; ni < 4; ni++)
            #pragma unroll
            for (int e = 0; e < 4; e++) o[ni][e] = 0.f;
        #pragma unroll
        for (int ks = 0; ks < 4; ks++) {
            int kb = ks*8;
            uint32_t af[4];
            af[0] = ps[row*PS2 + kb + c4];
            af[1] = ps[(row+8)*PS2 + kb + c4];
            af[2] = ps[row*PS2 + kb + c4 + 4];
            af[3] = ps[(row+8)*PS2 + kb + c4 + 4];
            #pragma unroll
            for (int ni = 0; ni < 4; ni++) {
                uint32_t bf[2];
                bf[0] = vvT[(ni*8 + q8)*VS2 + kb + c4];
                bf[1] = vvT[(ni*8 + q8)*VS2 + kb + c4 + 4];
                mma_f16(o[ni], af, bf);
            }
        }

        // ---- store half2 ----
        #pragma unroll
        for (int ni = 0; ni < 4; ni++) {
            int d0 = ni*8 + 2*c4;
            if (rv0) {
                __half2 hv = __floats2half2_rn(o[ni][0]*inv0, o[ni][1]*inv0);
                *(__half2*)&out[(size_t)(bw*NTOK + row)*DIM + h*HD + d0] = hv;
            }
            if (rv1) {
                __half2 hv = __floats2half2_rn(o[ni][2]*inv1, o[ni][3]*inv1);
                *(__half2*)&out[(size_t)(bw*NTOK + row + 8)*DIM + h*HD + d0] = hv;
            }
        }
    }
}

// ---------------- launcher -----------------------------------------------------
extern "C" void kernel_launch(void* const* d_in, const int* in_sizes, int n_in,
                              void* d_out, int out_size) {
    const float* x      = (const float*)d_in[0];
    const float* n1w    = (const float*)d_in[1];
    const float* n1b    = (const float*)d_in[2];
    const float* qkv_w  = (const float*)d_in[3];
    const float* qkv_b  = (const float*)d_in[4];
    const float* proj_w = (const float*)d_in[5];
    const float* proj_b = (const float*)d_in[6];
    const float* btab   = (const float*)d_in[7];
    const float* n2w    = (const float*)d_in[8];
    const float* n2b    = (const float*)d_in[9];
    const float* fc1_w  = (const float*)d_in[10];
    const float* fc1_b  = (const float*)d_in[11];
    const float* fc2_w  = (const float*)d_in[12];
    const float* fc2_b  = (const float*)d_in[13];
    float* out = (float*)d_out;

    __half *xw, *qkvb, *att, *z, *hid, *wq, *wp, *w1, *w2, *tbl;
    float *x1;
    cudaGetSymbolAddress((void**)&xw,   g_xw);
    cudaGetSymbolAddress((void**)&qkvb, g_qkv);
    cudaGetSymbolAddress((void**)&att,  g_att);
    cudaGetSymbolAddress((void**)&x1,   g_x1);
    cudaGetSymbolAddress((void**)&z,    g_z);
    cudaGetSymbolAddress((void**)&hid,  g_hid);
    cudaGetSymbolAddress((void**)&wq,   g_wq);
    cudaGetSymbolAddress((void**)&wp,   g_wp);
    cudaGetSymbolAddress((void**)&w1,   g_w1);
    cudaGetSymbolAddress((void**)&w2,   g_w2);
    cudaGetSymbolAddress((void**)&tbl,  g_tbl);

    const int SMEM = 3 * SSZ * 4;   // 98304 bytes
    static bool attr_done = false;
    if (!attr_done) {
        cudaFuncSetAttribute(mma_gemm<0>, cudaFuncAttributeMaxDynamicSharedMemorySize, SMEM);
        cudaFuncSetAttribute(mma_gemm<1>, cudaFuncAttributeMaxDynamicSharedMemorySize, SMEM);
        cudaFuncSetAttribute(mma_gemm<2>, cudaFuncAttributeMaxDynamicSharedMemorySize, SMEM);
        cudaFuncSetAttribute(mma_gemm<3>, cudaFuncAttributeMaxDynamicSharedMemorySize, SMEM);
        attr_done = true;
    }

    const int n0 = 3*DIM*DIM/4, n1 = DIM*DIM/4, n2 = MLPH*DIM/4, n3 = DIM*MLPH/4;
    wprep_all<<<(n0+n1+n2+n3 + 255)/256, 256>>>(qkv_w, wq, n0, proj_w, wp, n1,
                                                fc1_w, w1, n2, fc2_w, w2, n3);
    tbuild_kernel<<<48, 256>>>(btab, tbl);

    // 1. LN1 + cyclic shift + window partition (half out, warp-per-row)
    ln_kernel<1><<<ROWS/4, 128>>>(x, n1w, n1b, xw);
    // 2. QKV projection (fp16 tensor cores, ldmatrix)
    mma_gemm<0><<<dim3((3*DIM)/128, ROWS/128), 128, SMEM>>>(xw, wq, qkv_b, nullptr, qkvb, ROWS, 3*DIM, DIM);
    // 3. windowed attention (fp16 tensor cores, 8 batches per block)
    attn_mma<<<dim3((BATCH/BPB)*NWIN, HEADS), 128>>>(qkvb, tbl, att);
    // 4. proj + window reverse + unshift + shortcut residual (f32 out)
    mma_gemm<3><<<dim3(DIM/128, ROWS/128), 128, SMEM>>>(att, wp, proj_b, x, x1, ROWS, DIM, DIM);
    // 5. LN2 (half out, warp-per-row)
    ln_kernel<0><<<ROWS/4, 128>>>(x1, n2w, n2b, z);
    // 6. fc1 + exact GELU (half out)
    mma_gemm<1><<<dim3(MLPH/128, ROWS/128), 128, SMEM>>>(z, w1, fc1_b, nullptr, hid, ROWS, MLPH, DIM);
    // 7. fc2 + residual -> final output (f32)
    mma_gemm<2><<<dim3(DIM/128, ROWS/128), 128, SMEM>>>(hid, w2, fc2_b, x1, out, ROWS, DIM, MLPH);
}